// round 6
// baseline (speedup 1.0000x reference)
#include <cuda_runtime.h>
#include <math.h>

#define NN 50000
#define EE 400000
typedef unsigned long long u64;

__device__ float g_xin [NN*256];
__device__ float g_esc [EE];
__device__ float g_xh  [NN*64];
__device__ float g_alpha[NN*8];
__device__ float g_aexp[EE*8];
__device__ float g_amax[NN*8];
__device__ float g_asum[NN*8];
__device__ float g_agg [NN*64];
__device__ float g_gat1[NN*64];
__device__ float g_xw  [NN*64];
__device__ float g_gcn1[NN*64];
__device__ float g_dinv[NN];
__device__ float g_h1  [NN*32];

__device__ __forceinline__ float tanha(float x){
    float y; asm("tanh.approx.f32 %0, %1;" : "=f"(y) : "f"(x)); return y;
}
__device__ __forceinline__ float sigm(float x){ return fmaf(tanha(0.5f*x), 0.5f, 0.5f); }
__device__ __forceinline__ u64 pack2(float x, float y){
    u64 r; asm("mov.b64 %0, {%1,%2};" : "=l"(r) : "f"(x), "f"(y)); return r;
}
__device__ __forceinline__ u64 ffma2(u64 a, u64 b, u64 c){
    u64 d; asm("fma.rn.f32x2 %0, %1, %2, %3;" : "=l"(d) : "l"(a), "l"(b), "l"(c)); return d;
}
__device__ __forceinline__ float2 unpack2(u64 v){
    float2 f; asm("mov.b64 {%0,%1}, %2;" : "=f"(f.x), "=f"(f.y) : "l"(v)); return f;
}
__device__ __forceinline__ void atomicMaxF(float* a, float v){
    if (v >= 0.f) atomicMax((int*)a, __float_as_int(v));
    else          atomicMin((unsigned int*)a, __float_as_uint(v));
}
__device__ __forceinline__ void redAdd4(float* p, float a, float b, float c, float d){
    asm volatile("red.global.add.v4.f32 [%0], {%1,%2,%3,%4};"
                 :: "l"(p), "f"(a), "f"(b), "f"(c), "f"(d) : "memory");
}

// ---- LSTM: 16 lanes per element, one hidden unit per lane; gates packed f32x2 ----
__global__ __launch_bounds__(256, 2) void lstm_kernel(
    const float* __restrict__ seq, const int* __restrict__ lens,
    const float* __restrict__ Wih, const float* __restrict__ Whh,
    const float* __restrict__ bvec, const float* __restrict__ dnnW,
    const float* __restrict__ dnnb, int B, int mode)
{
    int lane = threadIdx.x & 31;
    int u = lane & 15;
    unsigned gmask = (lane < 16) ? 0x0000FFFFu : 0xFFFF0000u;
    int gid = (blockIdx.x * blockDim.x + threadIdx.x) >> 4;
    int ngroups = (gridDim.x * blockDim.x) >> 4;

    // packed weights: pair (i,f) and (g,o). rows: i=u, f=16+u, g=32+u, o=48+u
    u64 wif[16], wgo[16];
#pragma unroll
    for (int j = 0; j < 16; j++){
        wif[j] = pack2(Whh[u*16 + j],      Whh[(16+u)*16 + j]);
        wgo[j] = pack2(Whh[(32+u)*16 + j], Whh[(48+u)*16 + j]);
    }
    u64 wi0if = pack2(Wih[u*2],        Wih[(16+u)*2]);
    u64 wi1if = pack2(Wih[u*2+1],      Wih[(16+u)*2+1]);
    u64 wi0go = pack2(Wih[(32+u)*2],   Wih[(48+u)*2]);
    u64 wi1go = pack2(Wih[(32+u)*2+1], Wih[(48+u)*2+1]);
    u64 bif   = pack2(bvec[u],    bvec[16+u]);
    u64 bgo   = pack2(bvec[32+u], bvec[48+u]);
    float dw  = (mode == 1) ? dnnW[u] : 0.f;
    float dbv = (mode == 1) ? dnnb[0] : 0.f;

    for (int e = gid; e < B; e += ngroups){
        float2 v = ((const float2*)seq)[(size_t)e*16 + u];
        int L = lens[e];
        float h = 0.f, c = 0.f;
        for (int t = 0; t < L; t++){
            float x0 = __shfl_sync(gmask, v.x, t, 16);
            float x1 = __shfl_sync(gmask, v.y, t, 16);
            u64 x0p = pack2(x0, x0), x1p = pack2(x1, x1);
            u64 gif = ffma2(x1p, wi1if, ffma2(x0p, wi0if, bif));
            u64 ggo = ffma2(x1p, wi1go, ffma2(x0p, wi0go, bgo));
#pragma unroll
            for (int j = 0; j < 16; j++){
                float hj = __shfl_sync(gmask, h, j, 16);
                u64 hp = pack2(hj, hj);
                gif = ffma2(hp, wif[j], gif);
                ggo = ffma2(hp, wgo[j], ggo);
            }
            float2 gif2 = unpack2(gif), ggo2 = unpack2(ggo);
            c = fmaf(sigm(gif2.y), c, sigm(gif2.x) * tanha(ggo2.x));
            h = sigm(ggo2.y) * tanha(c);
        }
        if (mode == 0){
            g_xin[(size_t)e*256 + 240 + u] = h;
        } else {
            float val = h * dw;
#pragma unroll
            for (int off = 8; off; off >>= 1) val += __shfl_xor_sync(gmask, val, off, 16);
            if (u == 0) g_esc[e] = val + dbv;
        }
    }
}

__global__ void copy_x_kernel(const float* __restrict__ x){
    int i = blockIdx.x * blockDim.x + threadIdx.x;
    if (i >= NN*60) return;
    int r = i / 60, cq = i % 60;
    ((float4*)g_xin)[r*64 + cq] = ((const float4*)x)[i];
}
__global__ void fill_kernel(float* __restrict__ p, float v, int n){
    int i = blockIdx.x * blockDim.x + threadIdx.x;
    if (i < n) p[i] = v;
}

// ---- smem-staged GEMM: Out[M,64] = A[M,K] @ W[K,64], 4 rows x 4 cols per thread ----
__global__ __launch_bounds__(256) void gemm64_kernel(
    const float* __restrict__ A, int lda,
    const float* __restrict__ W, float* __restrict__ Out, int M, int K)
{
    __shared__ float sW[64*64];
    int tid = threadIdx.x;
    int c0 = (tid & 15) * 4;
    int r0 = blockIdx.x * 64 + (tid >> 4) * 4;
    float acc[4][4] = {};

    for (int kt = 0; kt < K; kt += 64){
        for (int i = tid; i < 64*16; i += 256)
            ((float4*)sW)[i] = ((const float4*)(W + (size_t)kt*64))[i];
        __syncthreads();
        for (int k = 0; k < 64; k += 4){
            float4 av[4];
#pragma unroll
            for (int r = 0; r < 4; r++){
                if (r0 + r < M) av[r] = *(const float4*)(A + (size_t)(r0+r)*lda + kt + k);
                else av[r] = make_float4(0.f,0.f,0.f,0.f);
            }
#pragma unroll
            for (int kk = 0; kk < 4; kk++){
                float4 w = *(float4*)(sW + (k+kk)*64 + c0);
#pragma unroll
                for (int r = 0; r < 4; r++){
                    float a = (&av[r].x)[kk];
                    acc[r][0] = fmaf(a, w.x, acc[r][0]);
                    acc[r][1] = fmaf(a, w.y, acc[r][1]);
                    acc[r][2] = fmaf(a, w.z, acc[r][2]);
                    acc[r][3] = fmaf(a, w.w, acc[r][3]);
                }
            }
        }
        __syncthreads();
    }
#pragma unroll
    for (int r = 0; r < 4; r++)
        if (r0 + r < M)
            *(float4*)(Out + (size_t)(r0+r)*64 + c0) =
                make_float4(acc[r][0], acc[r][1], acc[r][2], acc[r][3]);
}

// ---- GAT ----
__global__ void alpha_kernel(const float* __restrict__ att, int H){
    int i = blockIdx.x * blockDim.x + threadIdx.x;
    if (i >= NN*H) return;
    int n = i / H, h = i - n*H;
    int C = 64 / H;
    const float* xr = g_xh + (size_t)n*64 + h*C;
    const float* ar = att + h*C;
    float s = 0.f;
    for (int c = 0; c < C; c++) s = fmaf(xr[c], ar[c], s);
    g_alpha[i] = s;
    g_amax[i] = -INFINITY;     // fused init for the scatter phase
    g_asum[i] = 0.f;
}
__global__ void gatA_kernel(const int* __restrict__ ei, int H){
    int t = blockIdx.x * blockDim.x + threadIdx.x;
    if (t >= EE*H) return;
    int e = t / H, h = t - e*H;
    int s = ei[e], d = ei[EE+e];
    float a = g_alpha[s*H + h];
    a = a > 0.f ? a : 0.2f*a;
    g_aexp[e*H + h] = a;
    atomicMaxF(&g_amax[d*H + h], a);
}
__global__ void gatB_kernel(const int* __restrict__ ei, int H){
    int t = blockIdx.x * blockDim.x + threadIdx.x;
    if (t >= EE*H) return;
    int e = t / H, h = t - e*H;
    int d = ei[EE+e];
    float ex = __expf(g_aexp[e*H + h] - g_amax[d*H + h]);
    g_aexp[e*H + h] = ex;
    atomicAdd(&g_asum[d*H + h], ex);
}
__global__ void gatC_kernel(const int* __restrict__ ei, int H){
    int t = blockIdx.x * blockDim.x + threadIdx.x;
    int e = t >> 4;
    if (e >= EE) return;
    int l = t & 15;
    int s = ei[e], d = ei[EE+e];
    int h = (l*4*H) >> 6;
    float coef = __fdividef(g_aexp[e*H + h], g_asum[d*H + h]) + g_esc[e];
    float4 xv = *(const float4*)(g_xh + (size_t)s*64 + l*4);
    redAdd4(g_agg + (size_t)d*64 + l*4, xv.x*coef, xv.y*coef, xv.z*coef, xv.w*coef);
}
__global__ void gatFin_kernel(const float* __restrict__ bias, float* __restrict__ outp, int clean){
    int i = blockIdx.x * blockDim.x + threadIdx.x;
    if (i >= NN*64) return;
    int c = i & 63;
    float v = g_agg[i] + g_xh[i] + bias[c];
    g_agg[i] = 0.f;                       // reset for next scatter stage
    if (clean && !isfinite(v)) v = 0.f;
    outp[i] = v;
}

// ---- GCN ----
__global__ void deg_kernel(const int* __restrict__ ei){
    int e = blockIdx.x * blockDim.x + threadIdx.x;
    if (e < EE) atomicAdd(&g_dinv[ei[EE+e]], 1.f);
}
__global__ void dinv_kernel(){
    int n = blockIdx.x * blockDim.x + threadIdx.x;
    if (n < NN) g_dinv[n] = rsqrtf(g_dinv[n] + 1.f);
}
__global__ void gcnE_kernel(const int* __restrict__ ei){
    int t = blockIdx.x * blockDim.x + threadIdx.x;
    int e = t >> 4;
    if (e >= EE) return;
    int l = t & 15;
    int s = ei[e], d = ei[EE+e];
    float nm = g_dinv[s] * g_dinv[d];
    float4 xv = *(const float4*)(g_xw + (size_t)s*64 + l*4);
    redAdd4(g_agg + (size_t)d*64 + l*4, xv.x*nm, xv.y*nm, xv.z*nm, xv.w*nm);
}
__global__ void gcnFin_kernel(const float* __restrict__ bias, float* __restrict__ outp){
    int i = blockIdx.x * blockDim.x + threadIdx.x;
    if (i >= NN*64) return;
    int n = i >> 6, c = i & 63;
    float di = g_dinv[n];
    float v = g_agg[i] + g_xw[i]*di*di + bias[c];
    g_agg[i] = 0.f;                       // reset for next scatter stage
    outp[i] = v > 0.f ? v : 0.01f*v;
}

// ---- classifier layer 1 (K-split 256+64 -> 32) ----
__global__ __launch_bounds__(256) void cls1_kernel(
    const float* __restrict__ A, const float* __restrict__ A2,
    const float* __restrict__ W, const float* __restrict__ bias)
{
    int tid = threadIdx.x;
    int c0 = (tid & 7) * 4;
    int r0 = blockIdx.x * 64 + (tid >> 3) * 2;
    float acc[2][4] = {};
    for (int k = 0; k < 320; k += 4){
        float a0[4], a1[4];
        const float *p0, *p1;
        if (k < 256){ p0 = A  + (size_t)r0*256 + k;       p1 = p0 + 256; }
        else        { p0 = A2 + (size_t)r0*64 + (k-256);  p1 = p0 + 64; }
        bool v0 = r0 < NN, v1 = r0 + 1 < NN;
        if (v0) *(float4*)a0 = *(const float4*)p0; else *(float4*)a0 = make_float4(0,0,0,0);
        if (v1) *(float4*)a1 = *(const float4*)p1; else *(float4*)a1 = make_float4(0,0,0,0);
#pragma unroll
        for (int kk = 0; kk < 4; kk++){
            float4 w = *(const float4*)(W + (size_t)(k+kk)*32 + c0);
            acc[0][0]=fmaf(a0[kk],w.x,acc[0][0]); acc[0][1]=fmaf(a0[kk],w.y,acc[0][1]);
            acc[0][2]=fmaf(a0[kk],w.z,acc[0][2]); acc[0][3]=fmaf(a0[kk],w.w,acc[0][3]);
            acc[1][0]=fmaf(a1[kk],w.x,acc[1][0]); acc[1][1]=fmaf(a1[kk],w.y,acc[1][1]);
            acc[1][2]=fmaf(a1[kk],w.z,acc[1][2]); acc[1][3]=fmaf(a1[kk],w.w,acc[1][3]);
        }
    }
#pragma unroll
    for (int r = 0; r < 2; r++){
        if (r0 + r >= NN) break;
#pragma unroll
        for (int i = 0; i < 4; i++){
            float v = acc[r][i] + bias[c0+i];
            acc[r][i] = v > 0.f ? v : 0.01f*v;
        }
        *(float4*)(g_h1 + (size_t)(r0+r)*32 + c0) =
            make_float4(acc[r][0], acc[r][1], acc[r][2], acc[r][3]);
    }
}

// ---- classifier layers 2+3 ----
__global__ void cls23_kernel(const float* __restrict__ W2, const float* __restrict__ b2,
                             const float* __restrict__ W3, const float* __restrict__ b3,
                             float* __restrict__ out){
    __shared__ float sW2[32*16], sW3[16*4], sb2[16], sb3[4];
    for (int i = threadIdx.x; i < 512; i += 256) sW2[i] = W2[i];
    for (int i = threadIdx.x; i < 64;  i += 256) sW3[i] = W3[i];
    if (threadIdx.x < 16) sb2[threadIdx.x] = b2[threadIdx.x];
    if (threadIdx.x < 4)  sb3[threadIdx.x] = b3[threadIdx.x];
    __syncthreads();
    int n = blockIdx.x * blockDim.x + threadIdx.x;
    if (n >= NN) return;
    float h2[16];
#pragma unroll
    for (int j = 0; j < 16; j++) h2[j] = sb2[j];
#pragma unroll
    for (int q = 0; q < 8; q++){
        float4 hv = *(const float4*)(g_h1 + (size_t)n*32 + q*4);
        float hh[4] = {hv.x, hv.y, hv.z, hv.w};
#pragma unroll
        for (int kk = 0; kk < 4; kk++)
#pragma unroll
            for (int j = 0; j < 16; j++) h2[j] = fmaf(hh[kk], sW2[(q*4+kk)*16 + j], h2[j]);
    }
#pragma unroll
    for (int j = 0; j < 16; j++) h2[j] = h2[j] > 0.f ? h2[j] : 0.01f*h2[j];
    float o[4] = {sb3[0], sb3[1], sb3[2], sb3[3]};
#pragma unroll
    for (int k = 0; k < 16; k++)
#pragma unroll
        for (int j = 0; j < 4; j++) o[j] = fmaf(h2[k], sW3[k*4 + j], o[j]);
    *(float4*)(out + (size_t)n*4) = make_float4(o[0], o[1], o[2], o[3]);
}

extern "C" void kernel_launch(void* const* d_in, const int* in_sizes, int n_in,
                              void* d_out, int out_size)
{
    const float* x    = (const float*)d_in[0];
    const float* eseq = (const float*)d_in[1];
    const float* nseq = (const float*)d_in[2];
    const float* Wih  = (const float*)d_in[3];
    const float* Whh  = (const float*)d_in[4];
    const float* lb   = (const float*)d_in[5];
    const float* dW   = (const float*)d_in[6];
    const float* dbv  = (const float*)d_in[7];
    const float* g1W  = (const float*)d_in[8];
    const float* g1att= (const float*)d_in[9];
    const float* g1b  = (const float*)d_in[10];
    const float* g2W  = (const float*)d_in[11];
    const float* g2att= (const float*)d_in[12];
    const float* g2b  = (const float*)d_in[13];
    const float* n1W  = (const float*)d_in[14];
    const float* n1b  = (const float*)d_in[15];
    const float* n2W  = (const float*)d_in[16];
    const float* n2b  = (const float*)d_in[17];
    const float* c1W  = (const float*)d_in[18];
    const float* c1b  = (const float*)d_in[19];
    const float* c2W  = (const float*)d_in[20];
    const float* c2b  = (const float*)d_in[21];
    const float* c3W  = (const float*)d_in[22];
    const float* c3b  = (const float*)d_in[23];
    const int*   ei   = (const int*)d_in[24];
    const int*   elen = (const int*)d_in[25];
    const int*   nlen = (const int*)d_in[26];

    float* out  = (float*)d_out;
    float* xgcn = out + (size_t)NN*4;
    float* xgat = xgcn + (size_t)NN*64;

    float *p_xin, *p_xh, *p_gat1, *p_xw, *p_gcn1, *p_agg, *p_dinv;
    cudaGetSymbolAddress((void**)&p_xin,  g_xin);
    cudaGetSymbolAddress((void**)&p_xh,   g_xh);
    cudaGetSymbolAddress((void**)&p_gat1, g_gat1);
    cudaGetSymbolAddress((void**)&p_xw,   g_xw);
    cudaGetSymbolAddress((void**)&p_gcn1, g_gcn1);
    cudaGetSymbolAddress((void**)&p_agg,  g_agg);
    cudaGetSymbolAddress((void**)&p_dinv, g_dinv);

    auto cdiv = [](int a, int b){ return (a + b - 1) / b; };

    // temporal branches + one-time zeroing of agg/dinv
    fill_kernel<<<cdiv(NN*64,256),256>>>(p_agg, 0.f, NN*64);
    fill_kernel<<<cdiv(NN,256),256>>>(p_dinv, 0.f, NN);
    lstm_kernel<<<512, 256>>>(nseq, nlen, Wih, Whh, lb, dW, dbv, NN, 0);
    copy_x_kernel<<<cdiv(NN*60,256), 256>>>(x);
    lstm_kernel<<<2048, 256>>>(eseq, elen, Wih, Whh, lb, dW, dbv, EE, 1);

    // GCN degree
    deg_kernel<<<cdiv(EE,256),256>>>(ei);
    dinv_kernel<<<cdiv(NN,256),256>>>();

    // GAT1 (H=8)
    gemm64_kernel<<<cdiv(NN,64),256>>>(p_xin, 256, g1W, p_xh, NN, 256);
    alpha_kernel<<<cdiv(NN*8,256),256>>>(g1att, 8);
    gatA_kernel<<<cdiv(EE*8,256),256>>>(ei, 8);
    gatB_kernel<<<cdiv(EE*8,256),256>>>(ei, 8);
    gatC_kernel<<<cdiv(EE*16,256),256>>>(ei, 8);
    gatFin_kernel<<<cdiv(NN*64,256),256>>>(g1b, p_gat1, 0);

    // GAT2 (H=1)
    gemm64_kernel<<<cdiv(NN,64),256>>>(p_gat1, 64, g2W, p_xh, NN, 64);
    alpha_kernel<<<cdiv(NN,256),256>>>(g2att, 1);
    gatA_kernel<<<cdiv(EE,256),256>>>(ei, 1);
    gatB_kernel<<<cdiv(EE,256),256>>>(ei, 1);
    gatC_kernel<<<cdiv(EE*16,256),256>>>(ei, 1);
    gatFin_kernel<<<cdiv(NN*64,256),256>>>(g2b, xgat, 1);

    // GCN1
    gemm64_kernel<<<cdiv(NN,64),256>>>(p_xin, 256, n1W, p_xw, NN, 256);
    gcnE_kernel<<<cdiv(EE*16,256),256>>>(ei);
    gcnFin_kernel<<<cdiv(NN*64,256),256>>>(n1b, p_gcn1);

    // GCN2
    gemm64_kernel<<<cdiv(NN,64),256>>>(p_gcn1, 64, n2W, p_xw, NN, 64);
    gcnE_kernel<<<cdiv(EE*16,256),256>>>(ei);
    gcnFin_kernel<<<cdiv(NN*64,256),256>>>(n2b, xgcn);

    // classifier
    cls1_kernel<<<cdiv(NN,64),256>>>(p_xin, xgcn, c1W, c1b);
    cls23_kernel<<<cdiv(NN,256),256>>>(c2W, c2b, c3W, c3b, out);
}

// round 7
// speedup vs baseline: 1.1298x; 1.1298x over previous
#include <cuda_runtime.h>
#include <math.h>

#define NN 50000
#define EE 400000
typedef unsigned long long u64;

__device__ float g_xin [NN*256];
__device__ float g_esc [EE];
__device__ float g_xh  [NN*64];
__device__ float g_alpha[NN*8];
__device__ float g_asum[NN*8];
__device__ float g_agg [NN*64];
__device__ float g_agg2[NN*64];
__device__ float g_gat1[NN*64];
__device__ float g_xw  [NN*64];
__device__ float g_gcn1[NN*64];
__device__ float g_dinv[NN];
__device__ float g_h1  [NN*32];

__device__ __forceinline__ float tanha(float x){
    float y; asm("tanh.approx.f32 %0, %1;" : "=f"(y) : "f"(x)); return y;
}
__device__ __forceinline__ float sigm(float x){ return fmaf(tanha(0.5f*x), 0.5f, 0.5f); }
__device__ __forceinline__ u64 pack2(float x, float y){
    u64 r; asm("mov.b64 %0, {%1,%2};" : "=l"(r) : "f"(x), "f"(y)); return r;
}
__device__ __forceinline__ u64 ffma2(u64 a, u64 b, u64 c){
    u64 d; asm("fma.rn.f32x2 %0, %1, %2, %3;" : "=l"(d) : "l"(a), "l"(b), "l"(c)); return d;
}
__device__ __forceinline__ float2 unpack2(u64 v){
    float2 f; asm("mov.b64 {%0,%1}, %2;" : "=f"(f.x), "=f"(f.y) : "l"(v)); return f;
}
__device__ __forceinline__ void redAdd4(float* p, float a, float b, float c, float d){
    asm volatile("red.global.add.v4.f32 [%0], {%1,%2,%3,%4};"
                 :: "l"(p), "f"(a), "f"(b), "f"(c), "f"(d) : "memory");
}

// ---- LSTM: 16 lanes per element, one hidden unit per lane; gates packed f32x2 ----
__global__ __launch_bounds__(256, 2) void lstm_kernel(
    const float* __restrict__ seq, const int* __restrict__ lens,
    const float* __restrict__ Wih, const float* __restrict__ Whh,
    const float* __restrict__ bvec, const float* __restrict__ dnnW,
    const float* __restrict__ dnnb, int B, int mode)
{
    int lane = threadIdx.x & 31;
    int u = lane & 15;
    unsigned gmask = (lane < 16) ? 0x0000FFFFu : 0xFFFF0000u;
    int gid = (blockIdx.x * blockDim.x + threadIdx.x) >> 4;
    int ngroups = (gridDim.x * blockDim.x) >> 4;

    u64 wif[16], wgo[16];
#pragma unroll
    for (int j = 0; j < 16; j++){
        wif[j] = pack2(Whh[u*16 + j],      Whh[(16+u)*16 + j]);
        wgo[j] = pack2(Whh[(32+u)*16 + j], Whh[(48+u)*16 + j]);
    }
    u64 wi0if = pack2(Wih[u*2],        Wih[(16+u)*2]);
    u64 wi1if = pack2(Wih[u*2+1],      Wih[(16+u)*2+1]);
    u64 wi0go = pack2(Wih[(32+u)*2],   Wih[(48+u)*2]);
    u64 wi1go = pack2(Wih[(32+u)*2+1], Wih[(48+u)*2+1]);
    u64 bif   = pack2(bvec[u],    bvec[16+u]);
    u64 bgo   = pack2(bvec[32+u], bvec[48+u]);
    float dw  = (mode == 1) ? dnnW[u] : 0.f;
    float dbv = (mode == 1) ? dnnb[0] : 0.f;

    for (int e = gid; e < B; e += ngroups){
        float2 v = ((const float2*)seq)[(size_t)e*16 + u];
        int L = lens[e];
        float h = 0.f, c = 0.f;
        for (int t = 0; t < L; t++){
            float x0 = __shfl_sync(gmask, v.x, t, 16);
            float x1 = __shfl_sync(gmask, v.y, t, 16);
            u64 x0p = pack2(x0, x0), x1p = pack2(x1, x1);
            u64 gif = ffma2(x1p, wi1if, ffma2(x0p, wi0if, bif));
            u64 ggo = ffma2(x1p, wi1go, ffma2(x0p, wi0go, bgo));
#pragma unroll
            for (int j = 0; j < 16; j++){
                float hj = __shfl_sync(gmask, h, j, 16);
                u64 hp = pack2(hj, hj);
                gif = ffma2(hp, wif[j], gif);
                ggo = ffma2(hp, wgo[j], ggo);
            }
            float2 gif2 = unpack2(gif), ggo2 = unpack2(ggo);
            c = fmaf(sigm(gif2.y), c, sigm(gif2.x) * tanha(ggo2.x));
            h = sigm(ggo2.y) * tanha(c);
        }
        if (mode == 0){
            g_xin[(size_t)e*256 + 240 + u] = h;
        } else {
            float val = h * dw;
#pragma unroll
            for (int off = 8; off; off >>= 1) val += __shfl_xor_sync(gmask, val, off, 16);
            if (u == 0) g_esc[e] = val + dbv;
        }
    }
}

__global__ void copy_x_kernel(const float* __restrict__ x){
    int i = blockIdx.x * blockDim.x + threadIdx.x;
    if (i >= NN*60) return;
    int r = i / 60, cq = i % 60;
    ((float4*)g_xin)[r*64 + cq] = ((const float4*)x)[i];
}
__global__ void fill_kernel(float* __restrict__ p, float v, int n){
    int i = blockIdx.x * blockDim.x + threadIdx.x;
    if (i < n) p[i] = v;
}

// ---- smem-staged GEMM (f32x2 packed): Out[M,64] = A[M,K] @ W[K,64] ----
__global__ __launch_bounds__(256) void gemm64_kernel(
    const float* __restrict__ A, int lda,
    const float* __restrict__ W, float* __restrict__ Out, int M, int K)
{
    __shared__ float sW[64*64];
    int tid = threadIdx.x;
    int c0 = (tid & 15) * 4;
    int r0 = blockIdx.x * 64 + (tid >> 4) * 4;
    u64 acc[4][2] = {};

    for (int kt = 0; kt < K; kt += 64){
        for (int i = tid; i < 64*16; i += 256)
            ((float4*)sW)[i] = ((const float4*)(W + (size_t)kt*64))[i];
        __syncthreads();
        for (int k = 0; k < 64; k += 4){
            float4 av[4];
#pragma unroll
            for (int r = 0; r < 4; r++){
                if (r0 + r < M) av[r] = *(const float4*)(A + (size_t)(r0+r)*lda + kt + k);
                else av[r] = make_float4(0.f,0.f,0.f,0.f);
            }
#pragma unroll
            for (int kk = 0; kk < 4; kk++){
                float4 w = *(float4*)(sW + (k+kk)*64 + c0);
                u64 w01 = pack2(w.x, w.y), w23 = pack2(w.z, w.w);
#pragma unroll
                for (int r = 0; r < 4; r++){
                    float a = (&av[r].x)[kk];
                    u64 ap = pack2(a, a);
                    acc[r][0] = ffma2(ap, w01, acc[r][0]);
                    acc[r][1] = ffma2(ap, w23, acc[r][1]);
                }
            }
        }
        __syncthreads();
    }
#pragma unroll
    for (int r = 0; r < 4; r++)
        if (r0 + r < M){
            float2 p0 = unpack2(acc[r][0]), p1 = unpack2(acc[r][1]);
            *(float4*)(Out + (size_t)(r0+r)*64 + c0) = make_float4(p0.x, p0.y, p1.x, p1.y);
        }
}

// ---- GAT (max-free softmax) ----
__global__ void alpha_kernel(const float* __restrict__ att, int H){
    int i = blockIdx.x * blockDim.x + threadIdx.x;
    if (i >= NN*H) return;
    int n = i / H, h = i - n*H;
    int C = 64 / H;
    const float* xr = g_xh + (size_t)n*64 + h*C;
    const float* ar = att + h*C;
    float s = 0.f;
    for (int c = 0; c < C; c++) s = fmaf(xr[c], ar[c], s);
    g_alpha[i] = s;
    g_asum[i] = 0.f;
}
__global__ void gatA_kernel(const int* __restrict__ ei, int H){
    int t = blockIdx.x * blockDim.x + threadIdx.x;
    if (t >= EE*H) return;
    int e = t / H, h = t - e*H;
    int s = ei[e], d = ei[EE+e];
    float a = g_alpha[s*H + h];
    a = a > 0.f ? a : 0.2f*a;
    atomicAdd(&g_asum[d*H + h], __expf(a));
}
__global__ void gatC_kernel(const int* __restrict__ ei, int H){
    int t = blockIdx.x * blockDim.x + threadIdx.x;
    int e = t >> 4;
    if (e >= EE) return;
    int l = t & 15;
    int s = ei[e], d = ei[EE+e];
    int h = (l*4*H) >> 6;
    float a = g_alpha[s*H + h];
    a = a > 0.f ? a : 0.2f*a;
    float coef = __fdividef(__expf(a), g_asum[d*H + h]) + g_esc[e];
    float4 xv = *(const float4*)(g_xh + (size_t)s*64 + l*4);
    redAdd4(g_agg + (size_t)d*64 + l*4, xv.x*coef, xv.y*coef, xv.z*coef, xv.w*coef);
}
__global__ void gatFin_kernel(const float* __restrict__ bias, float* __restrict__ outp, int clean){
    int i = blockIdx.x * blockDim.x + threadIdx.x;
    if (i >= NN*64) return;
    int c = i & 63;
    float v = g_agg[i] + g_xh[i] + bias[c];
    g_agg[i] = 0.f;
    if (clean && !isfinite(v)) v = 0.f;
    outp[i] = v;
}

// ---- GCN ----
__global__ void deg_kernel(const int* __restrict__ ei){
    int e = blockIdx.x * blockDim.x + threadIdx.x;
    if (e < EE) atomicAdd(&g_dinv[ei[EE+e]], 1.f);
}
__global__ void dinv_kernel(){
    int n = blockIdx.x * blockDim.x + threadIdx.x;
    if (n < NN) g_dinv[n] = rsqrtf(g_dinv[n] + 1.f);
}
__global__ void gcnE_kernel(const int* __restrict__ ei){
    int t = blockIdx.x * blockDim.x + threadIdx.x;
    int e = t >> 4;
    if (e >= EE) return;
    int l = t & 15;
    int s = ei[e], d = ei[EE+e];
    float nm = g_dinv[s] * g_dinv[d];
    float4 xv = *(const float4*)(g_xw + (size_t)s*64 + l*4);
    redAdd4(g_agg2 + (size_t)d*64 + l*4, xv.x*nm, xv.y*nm, xv.z*nm, xv.w*nm);
}
__global__ void gcnFin_kernel(const float* __restrict__ bias, float* __restrict__ outp){
    int i = blockIdx.x * blockDim.x + threadIdx.x;
    if (i >= NN*64) return;
    int n = i >> 6, c = i & 63;
    float di = g_dinv[n];
    float v = g_agg2[i] + g_xw[i]*di*di + bias[c];
    g_agg2[i] = 0.f;
    outp[i] = v > 0.f ? v : 0.01f*v;
}

// ---- classifier layer 1 (K-split 256+64 -> 32), f32x2 packed ----
__global__ __launch_bounds__(256) void cls1_kernel(
    const float* __restrict__ A, const float* __restrict__ A2,
    const float* __restrict__ W, const float* __restrict__ bias)
{
    int tid = threadIdx.x;
    int c0 = (tid & 7) * 4;
    int r0 = blockIdx.x * 64 + (tid >> 3) * 2;
    u64 acc[2][2] = {};
    for (int k = 0; k < 320; k += 4){
        float a0[4], a1[4];
        const float *p0, *p1;
        if (k < 256){ p0 = A  + (size_t)r0*256 + k;       p1 = p0 + 256; }
        else        { p0 = A2 + (size_t)r0*64 + (k-256);  p1 = p0 + 64; }
        bool v0 = r0 < NN, v1 = r0 + 1 < NN;
        if (v0) *(float4*)a0 = *(const float4*)p0; else { a0[0]=a0[1]=a0[2]=a0[3]=0.f; }
        if (v1) *(float4*)a1 = *(const float4*)p1; else { a1[0]=a1[1]=a1[2]=a1[3]=0.f; }
#pragma unroll
        for (int kk = 0; kk < 4; kk++){
            float4 w = *(const float4*)(W + (size_t)(k+kk)*32 + c0);
            u64 w01 = pack2(w.x, w.y), w23 = pack2(w.z, w.w);
            u64 ap0 = pack2(a0[kk], a0[kk]), ap1 = pack2(a1[kk], a1[kk]);
            acc[0][0] = ffma2(ap0, w01, acc[0][0]);
            acc[0][1] = ffma2(ap0, w23, acc[0][1]);
            acc[1][0] = ffma2(ap1, w01, acc[1][0]);
            acc[1][1] = ffma2(ap1, w23, acc[1][1]);
        }
    }
#pragma unroll
    for (int r = 0; r < 2; r++){
        if (r0 + r >= NN) break;
        float2 p0 = unpack2(acc[r][0]), p1 = unpack2(acc[r][1]);
        float vv[4] = {p0.x, p0.y, p1.x, p1.y};
#pragma unroll
        for (int i = 0; i < 4; i++){
            float v = vv[i] + bias[c0+i];
            vv[i] = v > 0.f ? v : 0.01f*v;
        }
        *(float4*)(g_h1 + (size_t)(r0+r)*32 + c0) = make_float4(vv[0], vv[1], vv[2], vv[3]);
    }
}

// ---- classifier layers 2+3 ----
__global__ void cls23_kernel(const float* __restrict__ W2, const float* __restrict__ b2,
                             const float* __restrict__ W3, const float* __restrict__ b3,
                             float* __restrict__ out){
    __shared__ float sW2[32*16], sW3[16*4], sb2[16], sb3[4];
    for (int i = threadIdx.x; i < 512; i += 256) sW2[i] = W2[i];
    for (int i = threadIdx.x; i < 64;  i += 256) sW3[i] = W3[i];
    if (threadIdx.x < 16) sb2[threadIdx.x] = b2[threadIdx.x];
    if (threadIdx.x < 4)  sb3[threadIdx.x] = b3[threadIdx.x];
    __syncthreads();
    int n = blockIdx.x * blockDim.x + threadIdx.x;
    if (n >= NN) return;
    float h2[16];
#pragma unroll
    for (int j = 0; j < 16; j++) h2[j] = sb2[j];
#pragma unroll
    for (int q = 0; q < 8; q++){
        float4 hv = *(const float4*)(g_h1 + (size_t)n*32 + q*4);
        float hh[4] = {hv.x, hv.y, hv.z, hv.w};
#pragma unroll
        for (int kk = 0; kk < 4; kk++)
#pragma unroll
            for (int j = 0; j < 16; j++) h2[j] = fmaf(hh[kk], sW2[(q*4+kk)*16 + j], h2[j]);
    }
#pragma unroll
    for (int j = 0; j < 16; j++) h2[j] = h2[j] > 0.f ? h2[j] : 0.01f*h2[j];
    float o[4] = {sb3[0], sb3[1], sb3[2], sb3[3]};
#pragma unroll
    for (int k = 0; k < 16; k++)
#pragma unroll
        for (int j = 0; j < 4; j++) o[j] = fmaf(h2[k], sW3[k*4 + j], o[j]);
    *(float4*)(out + (size_t)n*4) = make_float4(o[0], o[1], o[2], o[3]);
}

extern "C" void kernel_launch(void* const* d_in, const int* in_sizes, int n_in,
                              void* d_out, int out_size)
{
    const float* x    = (const float*)d_in[0];
    const float* eseq = (const float*)d_in[1];
    const float* nseq = (const float*)d_in[2];
    const float* Wih  = (const float*)d_in[3];
    const float* Whh  = (const float*)d_in[4];
    const float* lb   = (const float*)d_in[5];
    const float* dW   = (const float*)d_in[6];
    const float* dbv  = (const float*)d_in[7];
    const float* g1W  = (const float*)d_in[8];
    const float* g1att= (const float*)d_in[9];
    const float* g1b  = (const float*)d_in[10];
    const float* g2W  = (const float*)d_in[11];
    const float* g2att= (const float*)d_in[12];
    const float* g2b  = (const float*)d_in[13];
    const float* n1W  = (const float*)d_in[14];
    const float* n1b  = (const float*)d_in[15];
    const float* n2W  = (const float*)d_in[16];
    const float* n2b  = (const float*)d_in[17];
    const float* c1W  = (const float*)d_in[18];
    const float* c1b  = (const float*)d_in[19];
    const float* c2W  = (const float*)d_in[20];
    const float* c2b  = (const float*)d_in[21];
    const float* c3W  = (const float*)d_in[22];
    const float* c3b  = (const float*)d_in[23];
    const int*   ei   = (const int*)d_in[24];
    const int*   elen = (const int*)d_in[25];
    const int*   nlen = (const int*)d_in[26];

    float* out  = (float*)d_out;
    float* xgcn = out + (size_t)NN*4;
    float* xgat = xgcn + (size_t)NN*64;

    float *p_xin, *p_xh, *p_gat1, *p_xw, *p_gcn1, *p_agg, *p_agg2, *p_dinv;
    cudaGetSymbolAddress((void**)&p_xin,  g_xin);
    cudaGetSymbolAddress((void**)&p_xh,   g_xh);
    cudaGetSymbolAddress((void**)&p_gat1, g_gat1);
    cudaGetSymbolAddress((void**)&p_xw,   g_xw);
    cudaGetSymbolAddress((void**)&p_gcn1, g_gcn1);
    cudaGetSymbolAddress((void**)&p_agg,  g_agg);
    cudaGetSymbolAddress((void**)&p_agg2, g_agg2);
    cudaGetSymbolAddress((void**)&p_dinv, g_dinv);

    // one-time stream/event creation (outside capture: first call is the
    // correctness run, so these exist before the harness captures)
    static cudaStream_t s1 = nullptr, s2 = nullptr;
    static cudaEvent_t evRoot = nullptr, evEsc = nullptr, evXin = nullptr, evGcn = nullptr;
    if (!s1){
        cudaStreamCreateWithFlags(&s1, cudaStreamNonBlocking);
        cudaStreamCreateWithFlags(&s2, cudaStreamNonBlocking);
        cudaEventCreateWithFlags(&evRoot, cudaEventDisableTiming);
        cudaEventCreateWithFlags(&evEsc,  cudaEventDisableTiming);
        cudaEventCreateWithFlags(&evXin,  cudaEventDisableTiming);
        cudaEventCreateWithFlags(&evGcn,  cudaEventDisableTiming);
    }

    auto cdiv = [](int a, int b){ return (a + b - 1) / b; };
    cudaStream_t s0 = 0;   // legacy default stream = harness capture stream

    // fork
    cudaEventRecord(evRoot, s0);
    cudaStreamWaitEvent(s1, evRoot, 0);
    cudaStreamWaitEvent(s2, evRoot, 0);

    // ---- s1: edge LSTM -> esc ----
    lstm_kernel<<<2048, 256, 0, s1>>>(eseq, elen, Wih, Whh, lb, dW, dbv, EE, 1);
    cudaEventRecord(evEsc, s1);

    // ---- s0: node features + GAT chain ----
    fill_kernel<<<cdiv(NN*64,256),256,0,s0>>>(p_agg, 0.f, NN*64);
    lstm_kernel<<<512, 256, 0, s0>>>(nseq, nlen, Wih, Whh, lb, dW, dbv, NN, 0);
    copy_x_kernel<<<cdiv(NN*60,256), 256, 0, s0>>>(x);
    cudaEventRecord(evXin, s0);

    // GAT1 (H=8)
    gemm64_kernel<<<cdiv(NN,64),256,0,s0>>>(p_xin, 256, g1W, p_xh, NN, 256);
    alpha_kernel<<<cdiv(NN*8,256),256,0,s0>>>(g1att, 8);
    gatA_kernel<<<cdiv(EE*8,256),256,0,s0>>>(ei, 8);
    cudaStreamWaitEvent(s0, evEsc, 0);
    gatC_kernel<<<cdiv(EE*16,256),256,0,s0>>>(ei, 8);
    gatFin_kernel<<<cdiv(NN*64,256),256,0,s0>>>(g1b, p_gat1, 0);

    // GAT2 (H=1)
    gemm64_kernel<<<cdiv(NN,64),256,0,s0>>>(p_gat1, 64, g2W, p_xh, NN, 64);
    alpha_kernel<<<cdiv(NN,256),256,0,s0>>>(g2att, 1);
    gatA_kernel<<<cdiv(EE,256),256,0,s0>>>(ei, 1);
    gatC_kernel<<<cdiv(EE*16,256),256,0,s0>>>(ei, 1);
    gatFin_kernel<<<cdiv(NN*64,256),256,0,s0>>>(g2b, xgat, 1);

    // ---- s2: degree + GCN chain ----
    fill_kernel<<<cdiv(NN*64,256),256,0,s2>>>(p_agg2, 0.f, NN*64);
    fill_kernel<<<cdiv(NN,256),256,0,s2>>>(p_dinv, 0.f, NN);
    deg_kernel<<<cdiv(EE,256),256,0,s2>>>(ei);
    dinv_kernel<<<cdiv(NN,256),256,0,s2>>>();
    cudaStreamWaitEvent(s2, evXin, 0);
    gemm64_kernel<<<cdiv(NN,64),256,0,s2>>>(p_xin, 256, n1W, p_xw, NN, 256);
    gcnE_kernel<<<cdiv(EE*16,256),256,0,s2>>>(ei);
    gcnFin_kernel<<<cdiv(NN*64,256),256,0,s2>>>(n1b, p_gcn1);
    gemm64_kernel<<<cdiv(NN,64),256,0,s2>>>(p_gcn1, 64, n2W, p_xw, NN, 64);
    gcnE_kernel<<<cdiv(EE*16,256),256,0,s2>>>(ei);
    gcnFin_kernel<<<cdiv(NN*64,256),256,0,s2>>>(n2b, xgcn);
    cudaEventRecord(evGcn, s2);

    // ---- join + classifier ----
    cudaStreamWaitEvent(s0, evGcn, 0);
    cls1_kernel<<<cdiv(NN,64),256,0,s0>>>(p_xin, xgcn, c1W, c1b);
    cls23_kernel<<<cdiv(NN,256),256,0,s0>>>(c2W, c2b, c3W, c3b, out);
}

// round 8
// speedup vs baseline: 1.1640x; 1.0303x over previous
#include <cuda_runtime.h>
#include <math.h>

#define NN 50000
#define EE 400000
typedef unsigned long long u64;

__device__ float g_xin [NN*256];
__device__ float g_esc [EE];
__device__ float g_xh  [NN*64];
__device__ float g_alpha[NN*8];
__device__ float g_asum[NN*8];
__device__ float g_agg [NN*64];
__device__ float g_agg2[NN*64];
__device__ float g_gat1[NN*64];
__device__ float g_xw  [NN*64];
__device__ float g_gcn1[NN*64];
__device__ float g_dinv[NN];
__device__ float g_h1  [NN*32];

__device__ __forceinline__ float tanha(float x){
    float y; asm("tanh.approx.f32 %0, %1;" : "=f"(y) : "f"(x)); return y;
}
__device__ __forceinline__ float sigm(float x){ return fmaf(tanha(0.5f*x), 0.5f, 0.5f); }
__device__ __forceinline__ u64 pack2(float x, float y){
    u64 r; asm("mov.b64 %0, {%1,%2};" : "=l"(r) : "f"(x), "f"(y)); return r;
}
__device__ __forceinline__ u64 ffma2(u64 a, u64 b, u64 c){
    u64 d; asm("fma.rn.f32x2 %0, %1, %2, %3;" : "=l"(d) : "l"(a), "l"(b), "l"(c)); return d;
}
__device__ __forceinline__ float2 unpack2(u64 v){
    float2 f; asm("mov.b64 {%0,%1}, %2;" : "=f"(f.x), "=f"(f.y) : "l"(v)); return f;
}
__device__ __forceinline__ void redAdd4(float* p, float a, float b, float c, float d){
    asm volatile("red.global.add.v4.f32 [%0], {%1,%2,%3,%4};"
                 :: "l"(p), "f"(a), "f"(b), "f"(c), "f"(d) : "memory");
}

// ---- LSTM: 16 lanes per element, smem h-broadcast (no per-step shuffles) ----
__global__ __launch_bounds__(256, 2) void lstm_kernel(
    const float* __restrict__ seq, const int* __restrict__ lens,
    const float* __restrict__ Wih, const float* __restrict__ Whh,
    const float* __restrict__ bvec, const float* __restrict__ dnnW,
    const float* __restrict__ dnnb, int B, int mode)
{
    __shared__ float shh[8][2][2][16];   // [warp][buf][group][unit]
    __shared__ float sxx[8][2][32];      // [warp][group][2t+c]
    int tid = threadIdx.x;
    int w = tid >> 5, lane = tid & 31;
    int grp = lane >> 4, u = lane & 15;
    int gid = (blockIdx.x * blockDim.x + tid) >> 4;
    int ngroups = (gridDim.x * blockDim.x) >> 4;

    u64 wif[16], wgo[16];
#pragma unroll
    for (int j = 0; j < 16; j++){
        wif[j] = pack2(Whh[u*16 + j],      Whh[(16+u)*16 + j]);
        wgo[j] = pack2(Whh[(32+u)*16 + j], Whh[(48+u)*16 + j]);
    }
    u64 wi0if = pack2(Wih[u*2],        Wih[(16+u)*2]);
    u64 wi1if = pack2(Wih[u*2+1],      Wih[(16+u)*2+1]);
    u64 wi0go = pack2(Wih[(32+u)*2],   Wih[(48+u)*2]);
    u64 wi1go = pack2(Wih[(32+u)*2+1], Wih[(48+u)*2+1]);
    u64 bif   = pack2(bvec[u],    bvec[16+u]);
    u64 bgo   = pack2(bvec[32+u], bvec[48+u]);
    float dw  = (mode == 1) ? dnnW[u] : 0.f;
    float dbv = (mode == 1) ? dnnb[0] : 0.f;

    for (int e = gid; e < B; e += ngroups){
        float2 v = ((const float2*)seq)[(size_t)e*16 + u];
        int L = lens[e];
        int Lo = __shfl_xor_sync(0xffffffffu, L, 16);
        int Lm = L > Lo ? L : Lo;
        sxx[w][grp][2*u]   = v.x;
        sxx[w][grp][2*u+1] = v.y;
        shh[w][0][grp][u]  = 0.f;
        __syncwarp();

        float h = 0.f, c = 0.f;
        for (int t = 0; t < Lm; t++){
            int rb = t & 1;
            float2 xv = *(float2*)&sxx[w][grp][2*t];
            u64 x0p = pack2(xv.x, xv.x), x1p = pack2(xv.y, xv.y);
            u64 gif = ffma2(x1p, wi1if, ffma2(x0p, wi0if, bif));
            u64 ggo = ffma2(x1p, wi1go, ffma2(x0p, wi0go, bgo));
            float4 H0 = *(float4*)&shh[w][rb][grp][0];
            float4 H1 = *(float4*)&shh[w][rb][grp][4];
            float4 H2 = *(float4*)&shh[w][rb][grp][8];
            float4 H3 = *(float4*)&shh[w][rb][grp][12];
            float hj[16] = {H0.x,H0.y,H0.z,H0.w, H1.x,H1.y,H1.z,H1.w,
                            H2.x,H2.y,H2.z,H2.w, H3.x,H3.y,H3.z,H3.w};
#pragma unroll
            for (int j = 0; j < 16; j++){
                u64 hp = pack2(hj[j], hj[j]);
                gif = ffma2(hp, wif[j], gif);
                ggo = ffma2(hp, wgo[j], ggo);
            }
            float2 gif2 = unpack2(gif), ggo2 = unpack2(ggo);
            if (t < L){
                c = fmaf(sigm(gif2.y), c, sigm(gif2.x) * tanha(ggo2.x));
                h = sigm(ggo2.y) * tanha(c);
            }
            shh[w][rb^1][grp][u] = h;
            __syncwarp();
        }

        if (mode == 0){
            g_xin[(size_t)e*256 + 240 + u] = h;
        } else {
            float val = h * dw;
#pragma unroll
            for (int off = 8; off; off >>= 1)
                val += __shfl_xor_sync(0xffffffffu, val, off, 16);
            if (u == 0) g_esc[e] = val + dbv;
        }
        __syncwarp();
    }
}

__global__ void copy_x_kernel(const float* __restrict__ x){
    int i = blockIdx.x * blockDim.x + threadIdx.x;
    if (i >= NN*60) return;
    int r = i / 60, cq = i % 60;
    ((float4*)g_xin)[r*64 + cq] = ((const float4*)x)[i];
}
__global__ void fill_kernel(float* __restrict__ p, float v, int n){
    int i = blockIdx.x * blockDim.x + threadIdx.x;
    if (i < n) p[i] = v;
}

// ---- smem-staged GEMM (f32x2 packed): Out[M,64] = A[M,K] @ W[K,64] ----
__global__ __launch_bounds__(256) void gemm64_kernel(
    const float* __restrict__ A, int lda,
    const float* __restrict__ W, float* __restrict__ Out, int M, int K)
{
    __shared__ float sW[64*64];
    int tid = threadIdx.x;
    int c0 = (tid & 15) * 4;
    int r0 = blockIdx.x * 64 + (tid >> 4) * 4;
    u64 acc[4][2] = {};

    for (int kt = 0; kt < K; kt += 64){
        for (int i = tid; i < 64*16; i += 256)
            ((float4*)sW)[i] = ((const float4*)(W + (size_t)kt*64))[i];
        __syncthreads();
        for (int k = 0; k < 64; k += 4){
            float4 av[4];
#pragma unroll
            for (int r = 0; r < 4; r++){
                if (r0 + r < M) av[r] = *(const float4*)(A + (size_t)(r0+r)*lda + kt + k);
                else av[r] = make_float4(0.f,0.f,0.f,0.f);
            }
#pragma unroll
            for (int kk = 0; kk < 4; kk++){
                float4 w = *(float4*)(sW + (k+kk)*64 + c0);
                u64 w01 = pack2(w.x, w.y), w23 = pack2(w.z, w.w);
#pragma unroll
                for (int r = 0; r < 4; r++){
                    float a = (&av[r].x)[kk];
                    u64 ap = pack2(a, a);
                    acc[r][0] = ffma2(ap, w01, acc[r][0]);
                    acc[r][1] = ffma2(ap, w23, acc[r][1]);
                }
            }
        }
        __syncthreads();
    }
#pragma unroll
    for (int r = 0; r < 4; r++)
        if (r0 + r < M){
            float2 p0 = unpack2(acc[r][0]), p1 = unpack2(acc[r][1]);
            *(float4*)(Out + (size_t)(r0+r)*64 + c0) = make_float4(p0.x, p0.y, p1.x, p1.y);
        }
}

// ---- GAT (max-free softmax) ----
__global__ void alpha_kernel(const float* __restrict__ att, int H){
    int i = blockIdx.x * blockDim.x + threadIdx.x;
    if (i >= NN*H) return;
    int n = i / H, h = i - n*H;
    int C = 64 / H;
    const float* xr = g_xh + (size_t)n*64 + h*C;
    const float* ar = att + h*C;
    float s = 0.f;
    for (int c = 0; c < C; c++) s = fmaf(xr[c], ar[c], s);
    g_alpha[i] = s;
    g_asum[i] = 0.f;
}
__global__ void gatA_kernel(const int* __restrict__ ei, int H){
    int t = blockIdx.x * blockDim.x + threadIdx.x;
    if (t >= EE*H) return;
    int e = t / H, h = t - e*H;
    int s = ei[e], d = ei[EE+e];
    float a = g_alpha[s*H + h];
    a = a > 0.f ? a : 0.2f*a;
    atomicAdd(&g_asum[d*H + h], __expf(a));
}
__global__ void gatC_kernel(const int* __restrict__ ei, int H){
    int t = blockIdx.x * blockDim.x + threadIdx.x;
    int e = t >> 4;
    if (e >= EE) return;
    int l = t & 15;
    int s = ei[e], d = ei[EE+e];
    int h = (l*4*H) >> 6;
    float a = g_alpha[s*H + h];
    a = a > 0.f ? a : 0.2f*a;
    float coef = __fdividef(__expf(a), g_asum[d*H + h]) + g_esc[e];
    float4 xv = *(const float4*)(g_xh + (size_t)s*64 + l*4);
    redAdd4(g_agg + (size_t)d*64 + l*4, xv.x*coef, xv.y*coef, xv.z*coef, xv.w*coef);
}
__global__ void gatFin_kernel(const float* __restrict__ bias, float* __restrict__ outp, int clean){
    int i = blockIdx.x * blockDim.x + threadIdx.x;
    if (i >= NN*64) return;
    int c = i & 63;
    float v = g_agg[i] + g_xh[i] + bias[c];
    g_agg[i] = 0.f;
    if (clean && !isfinite(v)) v = 0.f;
    outp[i] = v;
}

// ---- GCN ----
__global__ void deg_kernel(const int* __restrict__ ei){
    int e = blockIdx.x * blockDim.x + threadIdx.x;
    if (e < EE) atomicAdd(&g_dinv[ei[EE+e]], 1.f);
}
__global__ void dinv_kernel(){
    int n = blockIdx.x * blockDim.x + threadIdx.x;
    if (n < NN) g_dinv[n] = rsqrtf(g_dinv[n] + 1.f);
}
__global__ void gcnE_kernel(const int* __restrict__ ei){
    int t = blockIdx.x * blockDim.x + threadIdx.x;
    int e = t >> 4;
    if (e >= EE) return;
    int l = t & 15;
    int s = ei[e], d = ei[EE+e];
    float nm = g_dinv[s] * g_dinv[d];
    float4 xv = *(const float4*)(g_xw + (size_t)s*64 + l*4);
    redAdd4(g_agg2 + (size_t)d*64 + l*4, xv.x*nm, xv.y*nm, xv.z*nm, xv.w*nm);
}
__global__ void gcnFin_kernel(const float* __restrict__ bias, float* __restrict__ outp){
    int i = blockIdx.x * blockDim.x + threadIdx.x;
    if (i >= NN*64) return;
    int n = i >> 6, c = i & 63;
    float di = g_dinv[n];
    float v = g_agg2[i] + g_xw[i]*di*di + bias[c];
    g_agg2[i] = 0.f;
    outp[i] = v > 0.f ? v : 0.01f*v;
}

// ---- classifier layer 1 (K-split 256+64 -> 32), f32x2 packed ----
__global__ __launch_bounds__(256) void cls1_kernel(
    const float* __restrict__ A, const float* __restrict__ A2,
    const float* __restrict__ W, const float* __restrict__ bias)
{
    int tid = threadIdx.x;
    int c0 = (tid & 7) * 4;
    int r0 = blockIdx.x * 64 + (tid >> 3) * 2;
    u64 acc[2][2] = {};
    for (int k = 0; k < 320; k += 4){
        float a0[4], a1[4];
        const float *p0, *p1;
        if (k < 256){ p0 = A  + (size_t)r0*256 + k;       p1 = p0 + 256; }
        else        { p0 = A2 + (size_t)r0*64 + (k-256);  p1 = p0 + 64; }
        bool v0 = r0 < NN, v1 = r0 + 1 < NN;
        if (v0) *(float4*)a0 = *(const float4*)p0; else { a0[0]=a0[1]=a0[2]=a0[3]=0.f; }
        if (v1) *(float4*)a1 = *(const float4*)p1; else { a1[0]=a1[1]=a1[2]=a1[3]=0.f; }
#pragma unroll
        for (int kk = 0; kk < 4; kk++){
            float4 w = *(const float4*)(W + (size_t)(k+kk)*32 + c0);
            u64 w01 = pack2(w.x, w.y), w23 = pack2(w.z, w.w);
            u64 ap0 = pack2(a0[kk], a0[kk]), ap1 = pack2(a1[kk], a1[kk]);
            acc[0][0] = ffma2(ap0, w01, acc[0][0]);
            acc[0][1] = ffma2(ap0, w23, acc[0][1]);
            acc[1][0] = ffma2(ap1, w01, acc[1][0]);
            acc[1][1] = ffma2(ap1, w23, acc[1][1]);
        }
    }
#pragma unroll
    for (int r = 0; r < 2; r++){
        if (r0 + r >= NN) break;
        float2 p0 = unpack2(acc[r][0]), p1 = unpack2(acc[r][1]);
        float vv[4] = {p0.x, p0.y, p1.x, p1.y};
#pragma unroll
        for (int i = 0; i < 4; i++){
            float v = vv[i] + bias[c0+i];
            vv[i] = v > 0.f ? v : 0.01f*v;
        }
        *(float4*)(g_h1 + (size_t)(r0+r)*32 + c0) = make_float4(vv[0], vv[1], vv[2], vv[3]);
    }
}

// ---- classifier layers 2+3 ----
__global__ void cls23_kernel(const float* __restrict__ W2, const float* __restrict__ b2,
                             const float* __restrict__ W3, const float* __restrict__ b3,
                             float* __restrict__ out){
    __shared__ float sW2[32*16], sW3[16*4], sb2[16], sb3[4];
    for (int i = threadIdx.x; i < 512; i += 256) sW2[i] = W2[i];
    for (int i = threadIdx.x; i < 64;  i += 256) sW3[i] = W3[i];
    if (threadIdx.x < 16) sb2[threadIdx.x] = b2[threadIdx.x];
    if (threadIdx.x < 4)  sb3[threadIdx.x] = b3[threadIdx.x];
    __syncthreads();
    int n = blockIdx.x * blockDim.x + threadIdx.x;
    if (n >= NN) return;
    float h2[16];
#pragma unroll
    for (int j = 0; j < 16; j++) h2[j] = sb2[j];
#pragma unroll
    for (int q = 0; q < 8; q++){
        float4 hv = *(const float4*)(g_h1 + (size_t)n*32 + q*4);
        float hh[4] = {hv.x, hv.y, hv.z, hv.w};
#pragma unroll
        for (int kk = 0; kk < 4; kk++)
#pragma unroll
            for (int j = 0; j < 16; j++) h2[j] = fmaf(hh[kk], sW2[(q*4+kk)*16 + j], h2[j]);
    }
#pragma unroll
    for (int j = 0; j < 16; j++) h2[j] = h2[j] > 0.f ? h2[j] : 0.01f*h2[j];
    float o[4] = {sb3[0], sb3[1], sb3[2], sb3[3]};
#pragma unroll
    for (int k = 0; k < 16; k++)
#pragma unroll
        for (int j = 0; j < 4; j++) o[j] = fmaf(h2[k], sW3[k*4 + j], o[j]);
    *(float4*)(out + (size_t)n*4) = make_float4(o[0], o[1], o[2], o[3]);
}

extern "C" void kernel_launch(void* const* d_in, const int* in_sizes, int n_in,
                              void* d_out, int out_size)
{
    const float* x    = (const float*)d_in[0];
    const float* eseq = (const float*)d_in[1];
    const float* nseq = (const float*)d_in[2];
    const float* Wih  = (const float*)d_in[3];
    const float* Whh  = (const float*)d_in[4];
    const float* lb   = (const float*)d_in[5];
    const float* dW   = (const float*)d_in[6];
    const float* dbv  = (const float*)d_in[7];
    const float* g1W  = (const float*)d_in[8];
    const float* g1att= (const float*)d_in[9];
    const float* g1b  = (const float*)d_in[10];
    const float* g2W  = (const float*)d_in[11];
    const float* g2att= (const float*)d_in[12];
    const float* g2b  = (const float*)d_in[13];
    const float* n1W  = (const float*)d_in[14];
    const float* n1b  = (const float*)d_in[15];
    const float* n2W  = (const float*)d_in[16];
    const float* n2b  = (const float*)d_in[17];
    const float* c1W  = (const float*)d_in[18];
    const float* c1b  = (const float*)d_in[19];
    const float* c2W  = (const float*)d_in[20];
    const float* c2b  = (const float*)d_in[21];
    const float* c3W  = (const float*)d_in[22];
    const float* c3b  = (const float*)d_in[23];
    const int*   ei   = (const int*)d_in[24];
    const int*   elen = (const int*)d_in[25];
    const int*   nlen = (const int*)d_in[26];

    float* out  = (float*)d_out;
    float* xgcn = out + (size_t)NN*4;
    float* xgat = xgcn + (size_t)NN*64;

    float *p_xin, *p_xh, *p_gat1, *p_xw, *p_gcn1, *p_agg, *p_agg2, *p_dinv;
    cudaGetSymbolAddress((void**)&p_xin,  g_xin);
    cudaGetSymbolAddress((void**)&p_xh,   g_xh);
    cudaGetSymbolAddress((void**)&p_gat1, g_gat1);
    cudaGetSymbolAddress((void**)&p_xw,   g_xw);
    cudaGetSymbolAddress((void**)&p_gcn1, g_gcn1);
    cudaGetSymbolAddress((void**)&p_agg,  g_agg);
    cudaGetSymbolAddress((void**)&p_agg2, g_agg2);
    cudaGetSymbolAddress((void**)&p_dinv, g_dinv);

    static cudaStream_t s1 = nullptr, s2 = nullptr;
    static cudaEvent_t evRoot = nullptr, evEsc = nullptr, evXin = nullptr, evGcn = nullptr;
    if (!s1){
        cudaStreamCreateWithFlags(&s1, cudaStreamNonBlocking);
        cudaStreamCreateWithFlags(&s2, cudaStreamNonBlocking);
        cudaEventCreateWithFlags(&evRoot, cudaEventDisableTiming);
        cudaEventCreateWithFlags(&evEsc,  cudaEventDisableTiming);
        cudaEventCreateWithFlags(&evXin,  cudaEventDisableTiming);
        cudaEventCreateWithFlags(&evGcn,  cudaEventDisableTiming);
    }

    auto cdiv = [](int a, int b){ return (a + b - 1) / b; };
    cudaStream_t s0 = 0;

    cudaEventRecord(evRoot, s0);
    cudaStreamWaitEvent(s1, evRoot, 0);
    cudaStreamWaitEvent(s2, evRoot, 0);

    // ---- s1: edge LSTM -> esc ----
    lstm_kernel<<<2048, 256, 0, s1>>>(eseq, elen, Wih, Whh, lb, dW, dbv, EE, 1);
    cudaEventRecord(evEsc, s1);

    // ---- s0: node features + GAT chain ----
    fill_kernel<<<cdiv(NN*64,256),256,0,s0>>>(p_agg, 0.f, NN*64);
    lstm_kernel<<<512, 256, 0, s0>>>(nseq, nlen, Wih, Whh, lb, dW, dbv, NN, 0);
    copy_x_kernel<<<cdiv(NN*60,256), 256, 0, s0>>>(x);
    cudaEventRecord(evXin, s0);

    // GAT1 (H=8)
    gemm64_kernel<<<cdiv(NN,64),256,0,s0>>>(p_xin, 256, g1W, p_xh, NN, 256);
    alpha_kernel<<<cdiv(NN*8,256),256,0,s0>>>(g1att, 8);
    gatA_kernel<<<cdiv(EE*8,256),256,0,s0>>>(ei, 8);
    cudaStreamWaitEvent(s0, evEsc, 0);
    gatC_kernel<<<cdiv(EE*16,256),256,0,s0>>>(ei, 8);
    gatFin_kernel<<<cdiv(NN*64,256),256,0,s0>>>(g1b, p_gat1, 0);

    // GAT2 (H=1)
    gemm64_kernel<<<cdiv(NN,64),256,0,s0>>>(p_gat1, 64, g2W, p_xh, NN, 64);
    alpha_kernel<<<cdiv(NN,256),256,0,s0>>>(g2att, 1);
    gatA_kernel<<<cdiv(EE,256),256,0,s0>>>(ei, 1);
    gatC_kernel<<<cdiv(EE*16,256),256,0,s0>>>(ei, 1);
    gatFin_kernel<<<cdiv(NN*64,256),256,0,s0>>>(g2b, xgat, 1);

    // ---- s2: degree + GCN chain ----
    fill_kernel<<<cdiv(NN*64,256),256,0,s2>>>(p_agg2, 0.f, NN*64);
    fill_kernel<<<cdiv(NN,256),256,0,s2>>>(p_dinv, 0.f, NN);
    deg_kernel<<<cdiv(EE,256),256,0,s2>>>(ei);
    dinv_kernel<<<cdiv(NN,256),256,0,s2>>>();
    cudaStreamWaitEvent(s2, evXin, 0);
    gemm64_kernel<<<cdiv(NN,64),256,0,s2>>>(p_xin, 256, n1W, p_xw, NN, 256);
    gcnE_kernel<<<cdiv(EE*16,256),256,0,s2>>>(ei);
    gcnFin_kernel<<<cdiv(NN*64,256),256,0,s2>>>(n1b, p_gcn1);
    gemm64_kernel<<<cdiv(NN,64),256,0,s2>>>(p_gcn1, 64, n2W, p_xw, NN, 64);
    gcnE_kernel<<<cdiv(EE*16,256),256,0,s2>>>(ei);
    gcnFin_kernel<<<cdiv(NN*64,256),256,0,s2>>>(n2b, xgcn);
    cudaEventRecord(evGcn, s2);

    // ---- join + classifier ----
    cudaStreamWaitEvent(s0, evGcn, 0);
    cls1_kernel<<<cdiv(NN,64),256,0,s0>>>(p_xin, xgcn, c1W, c1b);
    cls23_kernel<<<cdiv(NN,256),256,0,s0>>>(c2W, c2b, c3W, c3b, out);
}

// round 9
// speedup vs baseline: 1.5228x; 1.3083x over previous
#include <cuda_runtime.h>
#include <math.h>

#define NN 50000
#define EE 400000
typedef unsigned long long u64;

__device__ float g_xin [NN*256];
__device__ float g_esc [EE];
__device__ float g_xh  [NN*64];
__device__ float g_alpha[NN*8];
__device__ float g_gat1[NN*64];
__device__ float g_xw  [NN*64];
__device__ float g_gcn1[NN*64];
__device__ float g_dinv[NN];
__device__ float g_h1  [NN*32];
// CSR
__device__ int g_cnt[NN];
__device__ int g_off[NN+1];
__device__ int g_blk[256];
__device__ int g_adj[EE];

__device__ __forceinline__ float tanha(float x){
    float y; asm("tanh.approx.f32 %0, %1;" : "=f"(y) : "f"(x)); return y;
}
__device__ __forceinline__ float sigm(float x){ return fmaf(tanha(0.5f*x), 0.5f, 0.5f); }
__device__ __forceinline__ u64 pack2(float x, float y){
    u64 r; asm("mov.b64 %0, {%1,%2};" : "=l"(r) : "f"(x), "f"(y)); return r;
}
__device__ __forceinline__ u64 ffma2(u64 a, u64 b, u64 c){
    u64 d; asm("fma.rn.f32x2 %0, %1, %2, %3;" : "=l"(d) : "l"(a), "l"(b), "l"(c)); return d;
}
__device__ __forceinline__ float2 unpack2(u64 v){
    float2 f; asm("mov.b64 {%0,%1}, %2;" : "=f"(f.x), "=f"(f.y) : "l"(v)); return f;
}

// ---- LSTM: 16 lanes per element, smem h-broadcast ----
__global__ __launch_bounds__(256, 2) void lstm_kernel(
    const float* __restrict__ seq, const int* __restrict__ lens,
    const float* __restrict__ Wih, const float* __restrict__ Whh,
    const float* __restrict__ bvec, const float* __restrict__ dnnW,
    const float* __restrict__ dnnb, int B, int mode)
{
    __shared__ float shh[8][2][2][16];
    __shared__ float sxx[8][2][32];
    int tid = threadIdx.x;
    int w = tid >> 5, lane = tid & 31;
    int grp = lane >> 4, u = lane & 15;
    int gid = (blockIdx.x * blockDim.x + tid) >> 4;
    int ngroups = (gridDim.x * blockDim.x) >> 4;

    u64 wif[16], wgo[16];
#pragma unroll
    for (int j = 0; j < 16; j++){
        wif[j] = pack2(Whh[u*16 + j],      Whh[(16+u)*16 + j]);
        wgo[j] = pack2(Whh[(32+u)*16 + j], Whh[(48+u)*16 + j]);
    }
    u64 wi0if = pack2(Wih[u*2],        Wih[(16+u)*2]);
    u64 wi1if = pack2(Wih[u*2+1],      Wih[(16+u)*2+1]);
    u64 wi0go = pack2(Wih[(32+u)*2],   Wih[(48+u)*2]);
    u64 wi1go = pack2(Wih[(32+u)*2+1], Wih[(48+u)*2+1]);
    u64 bif   = pack2(bvec[u],    bvec[16+u]);
    u64 bgo   = pack2(bvec[32+u], bvec[48+u]);
    float dw  = (mode == 1) ? dnnW[u] : 0.f;
    float dbv = (mode == 1) ? dnnb[0] : 0.f;

    for (int e = gid; e < B; e += ngroups){
        float2 v = ((const float2*)seq)[(size_t)e*16 + u];
        int L = lens[e];
        int Lo = __shfl_xor_sync(0xffffffffu, L, 16);
        int Lm = L > Lo ? L : Lo;
        sxx[w][grp][2*u]   = v.x;
        sxx[w][grp][2*u+1] = v.y;
        shh[w][0][grp][u]  = 0.f;
        __syncwarp();

        float h = 0.f, c = 0.f;
        for (int t = 0; t < Lm; t++){
            int rb = t & 1;
            float2 xv = *(float2*)&sxx[w][grp][2*t];
            u64 x0p = pack2(xv.x, xv.x), x1p = pack2(xv.y, xv.y);
            u64 gif = ffma2(x1p, wi1if, ffma2(x0p, wi0if, bif));
            u64 ggo = ffma2(x1p, wi1go, ffma2(x0p, wi0go, bgo));
            float4 H0 = *(float4*)&shh[w][rb][grp][0];
            float4 H1 = *(float4*)&shh[w][rb][grp][4];
            float4 H2 = *(float4*)&shh[w][rb][grp][8];
            float4 H3 = *(float4*)&shh[w][rb][grp][12];
            float hj[16] = {H0.x,H0.y,H0.z,H0.w, H1.x,H1.y,H1.z,H1.w,
                            H2.x,H2.y,H2.z,H2.w, H3.x,H3.y,H3.z,H3.w};
#pragma unroll
            for (int j = 0; j < 16; j++){
                u64 hp = pack2(hj[j], hj[j]);
                gif = ffma2(hp, wif[j], gif);
                ggo = ffma2(hp, wgo[j], ggo);
            }
            float2 gif2 = unpack2(gif), ggo2 = unpack2(ggo);
            if (t < L){
                c = fmaf(sigm(gif2.y), c, sigm(gif2.x) * tanha(ggo2.x));
                h = sigm(ggo2.y) * tanha(c);
            }
            shh[w][rb^1][grp][u] = h;
            __syncwarp();
        }

        if (mode == 0){
            g_xin[(size_t)e*256 + 240 + u] = h;
        } else {
            float val = h * dw;
#pragma unroll
            for (int off = 8; off; off >>= 1)
                val += __shfl_xor_sync(0xffffffffu, val, off, 16);
            if (u == 0) g_esc[e] = val + dbv;
        }
        __syncwarp();
    }
}

__global__ void copy_x_kernel(const float* __restrict__ x){
    int i = blockIdx.x * blockDim.x + threadIdx.x;
    if (i >= NN*60) return;
    int r = i / 60, cq = i % 60;
    ((float4*)g_xin)[r*64 + cq] = ((const float4*)x)[i];
}

// ---- CSR build ----
__global__ void zerocnt_kernel(){
    int i = blockIdx.x * blockDim.x + threadIdx.x;
    if (i < NN) g_cnt[i] = 0;
}
__global__ void count_kernel(const int* __restrict__ ei){
    int e = blockIdx.x * blockDim.x + threadIdx.x;
    if (e < EE) atomicAdd(&g_cnt[ei[EE+e]], 1);
}
__device__ __forceinline__ int blockScanIncl(int v, int tid, int* wt){
    int lane = tid & 31, w = tid >> 5;
    for (int o = 1; o < 32; o <<= 1){
        int u = __shfl_up_sync(0xffffffffu, v, o);
        if (lane >= o) v += u;
    }
    if (lane == 31) wt[w] = v;
    __syncthreads();
    if (w == 0){
        int s = (lane < 8) ? wt[lane] : 0;
        for (int o = 1; o < 8; o <<= 1){
            int u = __shfl_up_sync(0xffffffffu, s, o);
            if (lane >= o) s += u;
        }
        if (lane < 8) wt[lane] = s;
    }
    __syncthreads();
    if (w > 0) v += wt[w-1];
    return v;
}
__global__ void scan1_kernel(){
    __shared__ int wt[8];
    int tid = threadIdx.x;
    int i = blockIdx.x * 256 + tid;
    int c = (i < NN) ? g_cnt[i] : 0;
    int incl = blockScanIncl(c, tid, wt);
    if (i < NN){
        g_off[i] = incl - c;
        g_dinv[i] = rsqrtf((float)c + 1.f);
        g_cnt[i] = 0;
    }
    if (tid == 255) g_blk[blockIdx.x] = incl;
}
__global__ void scan2_kernel(int nblk){
    __shared__ int wt[8];
    int tid = threadIdx.x;
    int v = (tid < nblk) ? g_blk[tid] : 0;
    int incl = blockScanIncl(v, tid, wt);
    if (tid < nblk) g_blk[tid] = incl - v;
}
__global__ void scan3_kernel(){
    int tid = threadIdx.x;
    int i = blockIdx.x * 256 + tid;
    if (i < NN) g_off[i] += g_blk[blockIdx.x];
    if (i == 0) g_off[NN] = EE;
}
__global__ void fillAdj_kernel(const int* __restrict__ ei){
    int e = blockIdx.x * blockDim.x + threadIdx.x;
    if (e >= EE) return;
    int d = ei[EE+e];
    int pos = g_off[d] + atomicAdd(&g_cnt[d], 1);
    g_adj[pos] = e;
}

// ---- smem-staged GEMM (f32x2): Out[M,64] = A[M,K] @ W[K,64] ----
__global__ __launch_bounds__(256) void gemm64_kernel(
    const float* __restrict__ A, int lda,
    const float* __restrict__ W, float* __restrict__ Out, int M, int K)
{
    __shared__ float sW[64*64];
    int tid = threadIdx.x;
    int c0 = (tid & 15) * 4;
    int r0 = blockIdx.x * 64 + (tid >> 4) * 4;
    u64 acc[4][2] = {};

    for (int kt = 0; kt < K; kt += 64){
        for (int i = tid; i < 64*16; i += 256)
            ((float4*)sW)[i] = ((const float4*)(W + (size_t)kt*64))[i];
        __syncthreads();
        for (int k = 0; k < 64; k += 4){
            float4 av[4];
#pragma unroll
            for (int r = 0; r < 4; r++){
                if (r0 + r < M) av[r] = *(const float4*)(A + (size_t)(r0+r)*lda + kt + k);
                else av[r] = make_float4(0.f,0.f,0.f,0.f);
            }
#pragma unroll
            for (int kk = 0; kk < 4; kk++){
                float4 w = *(float4*)(sW + (k+kk)*64 + c0);
                u64 w01 = pack2(w.x, w.y), w23 = pack2(w.z, w.w);
#pragma unroll
                for (int r = 0; r < 4; r++){
                    float a = (&av[r].x)[kk];
                    u64 ap = pack2(a, a);
                    acc[r][0] = ffma2(ap, w01, acc[r][0]);
                    acc[r][1] = ffma2(ap, w23, acc[r][1]);
                }
            }
        }
        __syncthreads();
    }
#pragma unroll
    for (int r = 0; r < 4; r++)
        if (r0 + r < M){
            float2 p0 = unpack2(acc[r][0]), p1 = unpack2(acc[r][1]);
            *(float4*)(Out + (size_t)(r0+r)*64 + c0) = make_float4(p0.x, p0.y, p1.x, p1.y);
        }
}

// ---- GAT: alpha + fused per-dst softmax/aggregate (CSR, no atomics) ----
__global__ void alpha_kernel(const float* __restrict__ att, int H){
    int i = blockIdx.x * blockDim.x + threadIdx.x;
    if (i >= NN*H) return;
    int n = i / H, h = i - n*H;
    int C = 64 / H;
    const float* xr = g_xh + (size_t)n*64 + h*C;
    const float* ar = att + h*C;
    float s = 0.f;
    for (int c = 0; c < C; c++) s = fmaf(xr[c], ar[c], s);
    g_alpha[i] = s;
}
__global__ void gatAgg_kernel(const int* __restrict__ ei,
                              const float* __restrict__ bias,
                              float* __restrict__ outp, int H, int clean){
    int t = blockIdx.x * blockDim.x + threadIdx.x;
    int n = t >> 4;
    if (n >= NN) return;
    int l = t & 15;
    int h = (l*4*H) >> 6;
    int beg = g_off[n], end = g_off[n+1];

    float sum = 0.f;
    for (int p = beg; p < end; p++){
        int s = ei[g_adj[p]];
        float a = g_alpha[s*H + h];
        a = a > 0.f ? a : 0.2f*a;
        sum += __expf(a);
    }
    float rinv = (end > beg) ? __fdividef(1.f, sum) : 0.f;

    float4 res = *(const float4*)(g_xh + (size_t)n*64 + l*4);
    float acc0 = res.x + bias[l*4], acc1 = res.y + bias[l*4+1];
    float acc2 = res.z + bias[l*4+2], acc3 = res.w + bias[l*4+3];
    for (int p = beg; p < end; p++){
        int e = g_adj[p];
        int s = ei[e];
        float a = g_alpha[s*H + h];
        a = a > 0.f ? a : 0.2f*a;
        float coef = fmaf(__expf(a), rinv, g_esc[e]);
        float4 xv = *(const float4*)(g_xh + (size_t)s*64 + l*4);
        acc0 = fmaf(xv.x, coef, acc0);
        acc1 = fmaf(xv.y, coef, acc1);
        acc2 = fmaf(xv.z, coef, acc2);
        acc3 = fmaf(xv.w, coef, acc3);
    }
    if (clean){
        if (!isfinite(acc0)) acc0 = 0.f;
        if (!isfinite(acc1)) acc1 = 0.f;
        if (!isfinite(acc2)) acc2 = 0.f;
        if (!isfinite(acc3)) acc3 = 0.f;
    }
    *(float4*)(outp + (size_t)n*64 + l*4) = make_float4(acc0, acc1, acc2, acc3);
}

// ---- GCN: fused per-dst aggregate (CSR, no atomics) ----
__global__ void gcnAgg_kernel(const int* __restrict__ ei,
                              const float* __restrict__ bias,
                              float* __restrict__ outp){
    int t = blockIdx.x * blockDim.x + threadIdx.x;
    int n = t >> 4;
    if (n >= NN) return;
    int l = t & 15;
    int beg = g_off[n], end = g_off[n+1];
    float di = g_dinv[n];

    float4 sv = *(const float4*)(g_xw + (size_t)n*64 + l*4);
    float dd = di * di;
    float acc0 = fmaf(sv.x, dd, bias[l*4]);
    float acc1 = fmaf(sv.y, dd, bias[l*4+1]);
    float acc2 = fmaf(sv.z, dd, bias[l*4+2]);
    float acc3 = fmaf(sv.w, dd, bias[l*4+3]);
    for (int p = beg; p < end; p++){
        int s = ei[g_adj[p]];
        float nm = g_dinv[s] * di;
        float4 xv = *(const float4*)(g_xw + (size_t)s*64 + l*4);
        acc0 = fmaf(xv.x, nm, acc0);
        acc1 = fmaf(xv.y, nm, acc1);
        acc2 = fmaf(xv.z, nm, acc2);
        acc3 = fmaf(xv.w, nm, acc3);
    }
    acc0 = acc0 > 0.f ? acc0 : 0.01f*acc0;
    acc1 = acc1 > 0.f ? acc1 : 0.01f*acc1;
    acc2 = acc2 > 0.f ? acc2 : 0.01f*acc2;
    acc3 = acc3 > 0.f ? acc3 : 0.01f*acc3;
    *(float4*)(outp + (size_t)n*64 + l*4) = make_float4(acc0, acc1, acc2, acc3);
}

// ---- classifier layer 1 (K-split 256+64 -> 32), f32x2 packed ----
__global__ __launch_bounds__(256) void cls1_kernel(
    const float* __restrict__ A, const float* __restrict__ A2,
    const float* __restrict__ W, const float* __restrict__ bias)
{
    int tid = threadIdx.x;
    int c0 = (tid & 7) * 4;
    int r0 = blockIdx.x * 64 + (tid >> 3) * 2;
    u64 acc[2][2] = {};
    for (int k = 0; k < 320; k += 4){
        float a0[4], a1[4];
        const float *p0, *p1;
        if (k < 256){ p0 = A  + (size_t)r0*256 + k;       p1 = p0 + 256; }
        else        { p0 = A2 + (size_t)r0*64 + (k-256);  p1 = p0 + 64; }
        bool v0 = r0 < NN, v1 = r0 + 1 < NN;
        if (v0) *(float4*)a0 = *(const float4*)p0; else { a0[0]=a0[1]=a0[2]=a0[3]=0.f; }
        if (v1) *(float4*)a1 = *(const float4*)p1; else { a1[0]=a1[1]=a1[2]=a1[3]=0.f; }
#pragma unroll
        for (int kk = 0; kk < 4; kk++){
            float4 w = *(const float4*)(W + (size_t)(k+kk)*32 + c0);
            u64 w01 = pack2(w.x, w.y), w23 = pack2(w.z, w.w);
            u64 ap0 = pack2(a0[kk], a0[kk]), ap1 = pack2(a1[kk], a1[kk]);
            acc[0][0] = ffma2(ap0, w01, acc[0][0]);
            acc[0][1] = ffma2(ap0, w23, acc[0][1]);
            acc[1][0] = ffma2(ap1, w01, acc[1][0]);
            acc[1][1] = ffma2(ap1, w23, acc[1][1]);
        }
    }
#pragma unroll
    for (int r = 0; r < 2; r++){
        if (r0 + r >= NN) break;
        float2 p0 = unpack2(acc[r][0]), p1 = unpack2(acc[r][1]);
        float vv[4] = {p0.x, p0.y, p1.x, p1.y};
#pragma unroll
        for (int i = 0; i < 4; i++){
            float v = vv[i] + bias[c0+i];
            vv[i] = v > 0.f ? v : 0.01f*v;
        }
        *(float4*)(g_h1 + (size_t)(r0+r)*32 + c0) = make_float4(vv[0], vv[1], vv[2], vv[3]);
    }
}

// ---- classifier layers 2+3 ----
__global__ void cls23_kernel(const float* __restrict__ W2, const float* __restrict__ b2,
                             const float* __restrict__ W3, const float* __restrict__ b3,
                             float* __restrict__ out){
    __shared__ float sW2[32*16], sW3[16*4], sb2[16], sb3[4];
    for (int i = threadIdx.x; i < 512; i += 256) sW2[i] = W2[i];
    for (int i = threadIdx.x; i < 64;  i += 256) sW3[i] = W3[i];
    if (threadIdx.x < 16) sb2[threadIdx.x] = b2[threadIdx.x];
    if (threadIdx.x < 4)  sb3[threadIdx.x] = b3[threadIdx.x];
    __syncthreads();
    int n = blockIdx.x * blockDim.x + threadIdx.x;
    if (n >= NN) return;
    float h2[16];
#pragma unroll
    for (int j = 0; j < 16; j++) h2[j] = sb2[j];
#pragma unroll
    for (int q = 0; q < 8; q++){
        float4 hv = *(const float4*)(g_h1 + (size_t)n*32 + q*4);
        float hh[4] = {hv.x, hv.y, hv.z, hv.w};
#pragma unroll
        for (int kk = 0; kk < 4; kk++)
#pragma unroll
            for (int j = 0; j < 16; j++) h2[j] = fmaf(hh[kk], sW2[(q*4+kk)*16 + j], h2[j]);
    }
#pragma unroll
    for (int j = 0; j < 16; j++) h2[j] = h2[j] > 0.f ? h2[j] : 0.01f*h2[j];
    float o[4] = {sb3[0], sb3[1], sb3[2], sb3[3]};
#pragma unroll
    for (int k = 0; k < 16; k++)
#pragma unroll
        for (int j = 0; j < 4; j++) o[j] = fmaf(h2[k], sW3[k*4 + j], o[j]);
    *(float4*)(out + (size_t)n*4) = make_float4(o[0], o[1], o[2], o[3]);
}

extern "C" void kernel_launch(void* const* d_in, const int* in_sizes, int n_in,
                              void* d_out, int out_size)
{
    const float* x    = (const float*)d_in[0];
    const float* eseq = (const float*)d_in[1];
    const float* nseq = (const float*)d_in[2];
    const float* Wih  = (const float*)d_in[3];
    const float* Whh  = (const float*)d_in[4];
    const float* lb   = (const float*)d_in[5];
    const float* dW   = (const float*)d_in[6];
    const float* dbv  = (const float*)d_in[7];
    const float* g1W  = (const float*)d_in[8];
    const float* g1att= (const float*)d_in[9];
    const float* g1b  = (const float*)d_in[10];
    const float* g2W  = (const float*)d_in[11];
    const float* g2att= (const float*)d_in[12];
    const float* g2b  = (const float*)d_in[13];
    const float* n1W  = (const float*)d_in[14];
    const float* n1b  = (const float*)d_in[15];
    const float* n2W  = (const float*)d_in[16];
    const float* n2b  = (const float*)d_in[17];
    const float* c1W  = (const float*)d_in[18];
    const float* c1b  = (const float*)d_in[19];
    const float* c2W  = (const float*)d_in[20];
    const float* c2b  = (const float*)d_in[21];
    const float* c3W  = (const float*)d_in[22];
    const float* c3b  = (const float*)d_in[23];
    const int*   ei   = (const int*)d_in[24];
    const int*   elen = (const int*)d_in[25];
    const int*   nlen = (const int*)d_in[26];

    float* out  = (float*)d_out;
    float* xgcn = out + (size_t)NN*4;
    float* xgat = xgcn + (size_t)NN*64;

    float *p_xin, *p_xh, *p_gat1, *p_xw, *p_gcn1;
    cudaGetSymbolAddress((void**)&p_xin,  g_xin);
    cudaGetSymbolAddress((void**)&p_xh,   g_xh);
    cudaGetSymbolAddress((void**)&p_gat1, g_gat1);
    cudaGetSymbolAddress((void**)&p_xw,   g_xw);
    cudaGetSymbolAddress((void**)&p_gcn1, g_gcn1);

    static cudaStream_t s1 = nullptr, s2 = nullptr;
    static cudaEvent_t evRoot = nullptr, evEsc = nullptr, evXin = nullptr,
                       evGcn = nullptr, evCsr = nullptr;
    if (!s1){
        cudaStreamCreateWithFlags(&s1, cudaStreamNonBlocking);
        cudaStreamCreateWithFlags(&s2, cudaStreamNonBlocking);
        cudaEventCreateWithFlags(&evRoot, cudaEventDisableTiming);
        cudaEventCreateWithFlags(&evEsc,  cudaEventDisableTiming);
        cudaEventCreateWithFlags(&evXin,  cudaEventDisableTiming);
        cudaEventCreateWithFlags(&evGcn,  cudaEventDisableTiming);
        cudaEventCreateWithFlags(&evCsr,  cudaEventDisableTiming);
    }

    auto cdiv = [](int a, int b){ return (a + b - 1) / b; };
    cudaStream_t s0 = 0;
    const int NBLK = cdiv(NN, 256);   // 196

    cudaEventRecord(evRoot, s0);
    cudaStreamWaitEvent(s1, evRoot, 0);
    cudaStreamWaitEvent(s2, evRoot, 0);

    // ---- s1: edge LSTM -> esc ----
    lstm_kernel<<<2048, 256, 0, s1>>>(eseq, elen, Wih, Whh, lb, dW, dbv, EE, 1);
    cudaEventRecord(evEsc, s1);

    // ---- s2: CSR build (also yields dinv) ----
    zerocnt_kernel<<<NBLK, 256, 0, s2>>>();
    count_kernel<<<cdiv(EE,256), 256, 0, s2>>>(ei);
    scan1_kernel<<<NBLK, 256, 0, s2>>>();
    scan2_kernel<<<1, 256, 0, s2>>>(NBLK);
    scan3_kernel<<<NBLK, 256, 0, s2>>>();
    fillAdj_kernel<<<cdiv(EE,256), 256, 0, s2>>>(ei);
    cudaEventRecord(evCsr, s2);

    // ---- s0: node features ----
    lstm_kernel<<<512, 256, 0, s0>>>(nseq, nlen, Wih, Whh, lb, dW, dbv, NN, 0);
    copy_x_kernel<<<cdiv(NN*60,256), 256, 0, s0>>>(x);
    cudaEventRecord(evXin, s0);

    // ---- s0: GAT chain ----
    gemm64_kernel<<<cdiv(NN,64),256,0,s0>>>(p_xin, 256, g1W, p_xh, NN, 256);
    alpha_kernel<<<cdiv(NN*8,256),256,0,s0>>>(g1att, 8);
    cudaStreamWaitEvent(s0, evCsr, 0);
    cudaStreamWaitEvent(s0, evEsc, 0);
    gatAgg_kernel<<<cdiv(NN*16,256),256,0,s0>>>(ei, g1b, p_gat1, 8, 0);
    gemm64_kernel<<<cdiv(NN,64),256,0,s0>>>(p_gat1, 64, g2W, p_xh, NN, 64);
    alpha_kernel<<<cdiv(NN,256),256,0,s0>>>(g2att, 1);
    gatAgg_kernel<<<cdiv(NN*16,256),256,0,s0>>>(ei, g2b, xgat, 1, 1);

    // ---- s2: GCN chain (needs xin + CSR) ----
    cudaStreamWaitEvent(s2, evXin, 0);
    gemm64_kernel<<<cdiv(NN,64),256,0,s2>>>(p_xin, 256, n1W, p_xw, NN, 256);
    gcnAgg_kernel<<<cdiv(NN*16,256),256,0,s2>>>(ei, n1b, p_gcn1);
    gemm64_kernel<<<cdiv(NN,64),256,0,s2>>>(p_gcn1, 64, n2W, p_xw, NN, 64);
    gcnAgg_kernel<<<cdiv(NN*16,256),256,0,s2>>>(ei, n2b, xgcn);
    cudaEventRecord(evGcn, s2);

    // ---- join + classifier ----
    cudaStreamWaitEvent(s0, evGcn, 0);
    cls1_kernel<<<cdiv(NN,64),256,0,s0>>>(p_xin, xgcn, c1W, c1b);
    cls23_kernel<<<cdiv(NN,256),256,0,s0>>>(c2W, c2b, c3W, c3b, out);
}

// round 13
// speedup vs baseline: 1.6395x; 1.0766x over previous
#include <cuda_runtime.h>
#include <cuda_bf16.h>
#include <math.h>

#define NN 50000
#define EE 400000
typedef unsigned long long u64;
typedef unsigned int u32;

__device__ float g_xin [NN*256];
__device__ float g_esc [EE];
__device__ float g_xh  [NN*64];
__device__ float g_alpha[NN*8];
__device__ float g_gat1[NN*64];
__device__ float g_xw  [NN*64];
__device__ float g_gcn1[NN*64];
__device__ float g_dinv[NN];
__device__ float g_h1  [NN*32];
// CSR
__device__ int g_cnt[NN];
__device__ int g_off[NN+1];
__device__ int g_blk[256];
__device__ int g_adj[EE];
// bf16 hi/lo transposed weight scratch
__device__ __nv_bfloat16 g_bh1[64*256], g_bl1[64*256];
__device__ __nv_bfloat16 g_bh2[64*64],  g_bl2[64*64];
__device__ __nv_bfloat16 g_bn1[64*256], g_bn1l[64*256];
__device__ __nv_bfloat16 g_bn2[64*64],  g_bn2l[64*64];
__device__ __nv_bfloat16 g_bc1[32*320], g_bc1l[32*320];

__device__ __forceinline__ float tanha(float x){
    float y; asm("tanh.approx.f32 %0, %1;" : "=f"(y) : "f"(x)); return y;
}
__device__ __forceinline__ float sigm(float x){ return fmaf(tanha(0.5f*x), 0.5f, 0.5f); }
__device__ __forceinline__ u64 pack2(float x, float y){
    u64 r; asm("mov.b64 %0, {%1,%2};" : "=l"(r) : "f"(x), "f"(y)); return r;
}
__device__ __forceinline__ u64 ffma2(u64 a, u64 b, u64 c){
    u64 d; asm("fma.rn.f32x2 %0, %1, %2, %3;" : "=l"(d) : "l"(a), "l"(b), "l"(c)); return d;
}
__device__ __forceinline__ float2 unpack2(u64 v){
    float2 f; asm("mov.b64 {%0,%1}, %2;" : "=f"(f.x), "=f"(f.y) : "l"(v)); return f;
}
__device__ __forceinline__ void mma16816(float* c, const u32* a, const u32* b){
    asm volatile("mma.sync.aligned.m16n8k16.row.col.f32.bf16.bf16.f32 "
        "{%0,%1,%2,%3}, {%4,%5,%6,%7}, {%8,%9}, {%0,%1,%2,%3};"
        : "+f"(c[0]), "+f"(c[1]), "+f"(c[2]), "+f"(c[3])
        : "r"(a[0]), "r"(a[1]), "r"(a[2]), "r"(a[3]), "r"(b[0]), "r"(b[1]));
}
__device__ __forceinline__ void split2(float2 v, u32& hi, u32& lo){
    __nv_bfloat162 h = __floats2bfloat162_rn(v.x, v.y);
    float rx = v.x - __bfloat162float(__low2bfloat16(h));
    float ry = v.y - __bfloat162float(__high2bfloat16(h));
    __nv_bfloat162 l = __floats2bfloat162_rn(rx, ry);
    hi = *(u32*)&h; lo = *(u32*)&l;
}

// ---- LSTM: 16 lanes per element, smem h-broadcast ----
__global__ __launch_bounds__(256, 2) void lstm_kernel(
    const float* __restrict__ seq, const int* __restrict__ lens,
    const float* __restrict__ Wih, const float* __restrict__ Whh,
    const float* __restrict__ bvec, const float* __restrict__ dnnW,
    const float* __restrict__ dnnb, int B, int mode)
{
    __shared__ float shh[8][2][2][16];
    __shared__ float sxx[8][2][32];
    int tid = threadIdx.x;
    int w = tid >> 5, lane = tid & 31;
    int grp = lane >> 4, u = lane & 15;
    int gid = (blockIdx.x * blockDim.x + tid) >> 4;
    int ngroups = (gridDim.x * blockDim.x) >> 4;

    u64 wif[16], wgo[16];
#pragma unroll
    for (int j = 0; j < 16; j++){
        wif[j] = pack2(Whh[u*16 + j],      Whh[(16+u)*16 + j]);
        wgo[j] = pack2(Whh[(32+u)*16 + j], Whh[(48+u)*16 + j]);
    }
    u64 wi0if = pack2(Wih[u*2],        Wih[(16+u)*2]);
    u64 wi1if = pack2(Wih[u*2+1],      Wih[(16+u)*2+1]);
    u64 wi0go = pack2(Wih[(32+u)*2],   Wih[(48+u)*2]);
    u64 wi1go = pack2(Wih[(32+u)*2+1], Wih[(48+u)*2+1]);
    u64 bif   = pack2(bvec[u],    bvec[16+u]);
    u64 bgo   = pack2(bvec[32+u], bvec[48+u]);
    float dw  = (mode == 1) ? dnnW[u] : 0.f;
    float dbv = (mode == 1) ? dnnb[0] : 0.f;

    for (int e = gid; e < B; e += ngroups){
        float2 v = ((const float2*)seq)[(size_t)e*16 + u];
        int L = lens[e];
        int Lo = __shfl_xor_sync(0xffffffffu, L, 16);
        int Lm = L > Lo ? L : Lo;
        sxx[w][grp][2*u]   = v.x;
        sxx[w][grp][2*u+1] = v.y;
        shh[w][0][grp][u]  = 0.f;
        __syncwarp();

        float h = 0.f, c = 0.f;
        for (int t = 0; t < Lm; t++){
            int rb = t & 1;
            float2 xv = *(float2*)&sxx[w][grp][2*t];
            u64 x0p = pack2(xv.x, xv.x), x1p = pack2(xv.y, xv.y);
            u64 gif = ffma2(x1p, wi1if, ffma2(x0p, wi0if, bif));
            u64 ggo = ffma2(x1p, wi1go, ffma2(x0p, wi0go, bgo));
            float4 H0 = *(float4*)&shh[w][rb][grp][0];
            float4 H1 = *(float4*)&shh[w][rb][grp][4];
            float4 H2 = *(float4*)&shh[w][rb][grp][8];
            float4 H3 = *(float4*)&shh[w][rb][grp][12];
            float hj[16] = {H0.x,H0.y,H0.z,H0.w, H1.x,H1.y,H1.z,H1.w,
                            H2.x,H2.y,H2.z,H2.w, H3.x,H3.y,H3.z,H3.w};
#pragma unroll
            for (int j = 0; j < 16; j++){
                u64 hp = pack2(hj[j], hj[j]);
                gif = ffma2(hp, wif[j], gif);
                ggo = ffma2(hp, wgo[j], ggo);
            }
            float2 gif2 = unpack2(gif), ggo2 = unpack2(ggo);
            if (t < L){
                c = fmaf(sigm(gif2.y), c, sigm(gif2.x) * tanha(ggo2.x));
                h = sigm(ggo2.y) * tanha(c);
            }
            shh[w][rb^1][grp][u] = h;
            __syncwarp();
        }

        if (mode == 0){
            g_xin[(size_t)e*256 + 240 + u] = h;
        } else {
            float val = h * dw;
#pragma unroll
            for (int off = 8; off; off >>= 1)
                val += __shfl_xor_sync(0xffffffffu, val, off, 16);
            if (u == 0) g_esc[e] = val + dbv;
        }
        __syncwarp();
    }
}

__global__ void copy_x_kernel(const float* __restrict__ x){
    int i = blockIdx.x * blockDim.x + threadIdx.x;
    if (i >= NN*60) return;
    int r = i / 60, cq = i % 60;
    ((float4*)g_xin)[r*64 + cq] = ((const float4*)x)[i];
}

// ---- weight split + transpose: W[K,N] fp32 -> hiT/loT[N,K] bf16 ----
__global__ void convw_kernel(const float* __restrict__ W, __nv_bfloat16* __restrict__ hiT,
                             __nv_bfloat16* __restrict__ loT, int K, int N){
    int i = blockIdx.x * blockDim.x + threadIdx.x;
    if (i >= K*N) return;
    int k = i / N, n = i - k*N;
    float v = W[i];
    __nv_bfloat16 h = __float2bfloat16(v);
    hiT[n*K + k] = h;
    loT[n*K + k] = __float2bfloat16(v - __bfloat162float(h));
}

// ---- CSR build ----
__global__ void zerocnt_kernel(){
    int i = blockIdx.x * blockDim.x + threadIdx.x;
    if (i < NN) g_cnt[i] = 0;
}
__global__ void count_kernel(const int* __restrict__ ei){
    int e = blockIdx.x * blockDim.x + threadIdx.x;
    if (e < EE) atomicAdd(&g_cnt[ei[EE+e]], 1);
}
__device__ __forceinline__ int blockScanIncl(int v, int tid, int* wt){
    int lane = tid & 31, w = tid >> 5;
    for (int o = 1; o < 32; o <<= 1){
        int u = __shfl_up_sync(0xffffffffu, v, o);
        if (lane >= o) v += u;
    }
    if (lane == 31) wt[w] = v;
    __syncthreads();
    if (w == 0){
        int s = (lane < 8) ? wt[lane] : 0;
        for (int o = 1; o < 8; o <<= 1){
            int u = __shfl_up_sync(0xffffffffu, s, o);
            if (lane >= o) s += u;
        }
        if (lane < 8) wt[lane] = s;
    }
    __syncthreads();
    if (w > 0) v += wt[w-1];
    return v;
}
__global__ void scan1_kernel(){
    __shared__ int wt[8];
    int tid = threadIdx.x;
    int i = blockIdx.x * 256 + tid;
    int c = (i < NN) ? g_cnt[i] : 0;
    int incl = blockScanIncl(c, tid, wt);
    if (i < NN){
        g_off[i] = incl - c;
        g_dinv[i] = rsqrtf((float)c + 1.f);
        g_cnt[i] = 0;
    }
    if (tid == 255) g_blk[blockIdx.x] = incl;
}
__global__ void scan2_kernel(int nblk){
    __shared__ int wt[8];
    int tid = threadIdx.x;
    int v = (tid < nblk) ? g_blk[tid] : 0;
    int incl = blockScanIncl(v, tid, wt);
    if (tid < nblk) g_blk[tid] = incl - v;
}
__global__ void scan3_kernel(){
    int tid = threadIdx.x;
    int i = blockIdx.x * 256 + tid;
    if (i < NN) g_off[i] += g_blk[blockIdx.x];
    if (i == 0) g_off[NN] = EE;
}
__global__ void fillAdj_kernel(const int* __restrict__ ei){
    int e = blockIdx.x * blockDim.x + threadIdx.x;
    if (e >= EE) return;
    int d = ei[EE+e];
    int pos = g_off[d] + atomicAdd(&g_cnt[d], 1);
    g_adj[pos] = e;
}

// ---- tensor-core GEMM: Out[M,N] = act(A[M,K(split)] @ W + bias), bf16 3-pass ----
template<int N>
__global__ __launch_bounds__(256) void gemm_tc_kernel(
    const float* __restrict__ A, int lda, int K1,
    const float* __restrict__ A2, int lda2,
    const __nv_bfloat16* __restrict__ BhT, const __nv_bfloat16* __restrict__ BlT,
    const float* __restrict__ bias, float* __restrict__ Out,
    int M, int K, int act)
{
    constexpr int NT = N/8;
    int tid = threadIdx.x;
    int w = tid >> 5, lane = tid & 31;
    int gr = lane >> 2, t = lane & 3;
    int rowbase = blockIdx.x*128 + w*16;
    int r0 = rowbase + gr, r1 = r0 + 8;
    int r0c = r0 < M ? r0 : M-1;
    int r1c = r1 < M ? r1 : M-1;
    float acc[NT][4];
#pragma unroll
    for (int i = 0; i < NT; i++){ acc[i][0]=acc[i][1]=acc[i][2]=acc[i][3]=0.f; }

    for (int k = 0; k < K; k += 16){
        const float *p0, *p1;
        if (k < K1){ p0 = A + (size_t)r0c*lda + k;         p1 = A + (size_t)r1c*lda + k; }
        else       { p0 = A2 + (size_t)r0c*lda2 + (k-K1);  p1 = A2 + (size_t)r1c*lda2 + (k-K1); }
        float2 x00 = *(const float2*)(p0 + 2*t);
        float2 x02 = *(const float2*)(p0 + 2*t + 8);
        float2 x10 = *(const float2*)(p1 + 2*t);
        float2 x12 = *(const float2*)(p1 + 2*t + 8);
        u32 ah[4], al[4];
        split2(x00, ah[0], al[0]);
        split2(x10, ah[1], al[1]);
        split2(x02, ah[2], al[2]);
        split2(x12, ah[3], al[3]);
#pragma unroll
        for (int nt = 0; nt < NT; nt++){
            int n = nt*8 + gr;
            u32 bh[2], bl[2];
            bh[0] = *(const u32*)(BhT + n*K + k + 2*t);
            bh[1] = *(const u32*)(BhT + n*K + k + 8 + 2*t);
            bl[0] = *(const u32*)(BlT + n*K + k + 2*t);
            bl[1] = *(const u32*)(BlT + n*K + k + 8 + 2*t);
            mma16816(acc[nt], ah, bh);
            mma16816(acc[nt], ah, bl);
            mma16816(acc[nt], al, bh);
        }
    }
#pragma unroll
    for (int nt = 0; nt < NT; nt++){
        int c = nt*8 + 2*t;
        float b0 = bias ? bias[c] : 0.f, b1 = bias ? bias[c+1] : 0.f;
        float v0 = acc[nt][0]+b0, v1 = acc[nt][1]+b1;
        float v2 = acc[nt][2]+b0, v3 = acc[nt][3]+b1;
        if (act){
            v0 = v0>0.f?v0:0.01f*v0; v1 = v1>0.f?v1:0.01f*v1;
            v2 = v2>0.f?v2:0.01f*v2; v3 = v3>0.f?v3:0.01f*v3;
        }
        if (r0 < M) *(float2*)(Out + (size_t)r0*N + c) = make_float2(v0, v1);
        if (r1 < M) *(float2*)(Out + (size_t)r1*N + c) = make_float2(v2, v3);
    }
}

// ---- GAT: alpha + fused per-dst softmax/aggregate (CSR, no atomics) ----
__global__ void alpha_kernel(const float* __restrict__ att, int H){
    int i = blockIdx.x * blockDim.x + threadIdx.x;
    if (i >= NN*H) return;
    int n = i / H, h = i - n*H;
    int C = 64 / H;
    const float* xr = g_xh + (size_t)n*64 + h*C;
    const float* ar = att + h*C;
    float s = 0.f;
    for (int c = 0; c < C; c++) s = fmaf(xr[c], ar[c], s);
    g_alpha[i] = s;
}
__global__ void gatAgg_kernel(const int* __restrict__ ei,
                              const float* __restrict__ bias,
                              float* __restrict__ outp, int H, int clean){
    int t = blockIdx.x * blockDim.x + threadIdx.x;
    int n = t >> 4;
    if (n >= NN) return;
    int l = t & 15;
    int h = (l*4*H) >> 6;
    int beg = g_off[n], end = g_off[n+1];

    float sum = 0.f;
    for (int p = beg; p < end; p++){
        int s = ei[g_adj[p]];
        float a = g_alpha[s*H + h];
        a = a > 0.f ? a : 0.2f*a;
        sum += __expf(a);
    }
    float rinv = (end > beg) ? __fdividef(1.f, sum) : 0.f;

    float4 res = *(const float4*)(g_xh + (size_t)n*64 + l*4);
    float acc0 = res.x + bias[l*4], acc1 = res.y + bias[l*4+1];
    float acc2 = res.z + bias[l*4+2], acc3 = res.w + bias[l*4+3];
    for (int p = beg; p < end; p++){
        int e = g_adj[p];
        int s = ei[e];
        float a = g_alpha[s*H + h];
        a = a > 0.f ? a : 0.2f*a;
        float coef = fmaf(__expf(a), rinv, g_esc[e]);
        float4 xv = *(const float4*)(g_xh + (size_t)s*64 + l*4);
        acc0 = fmaf(xv.x, coef, acc0);
        acc1 = fmaf(xv.y, coef, acc1);
        acc2 = fmaf(xv.z, coef, acc2);
        acc3 = fmaf(xv.w, coef, acc3);
    }
    if (clean){
        if (!isfinite(acc0)) acc0 = 0.f;
        if (!isfinite(acc1)) acc1 = 0.f;
        if (!isfinite(acc2)) acc2 = 0.f;
        if (!isfinite(acc3)) acc3 = 0.f;
    }
    *(float4*)(outp + (size_t)n*64 + l*4) = make_float4(acc0, acc1, acc2, acc3);
}

// ---- GCN: fused per-dst aggregate (CSR, no atomics) ----
__global__ void gcnAgg_kernel(const int* __restrict__ ei,
                              const float* __restrict__ bias,
                              float* __restrict__ outp){
    int t = blockIdx.x * blockDim.x + threadIdx.x;
    int n = t >> 4;
    if (n >= NN) return;
    int l = t & 15;
    int beg = g_off[n], end = g_off[n+1];
    float di = g_dinv[n];

    float4 sv = *(const float4*)(g_xw + (size_t)n*64 + l*4);
    float dd = di * di;
    float acc0 = fmaf(sv.x, dd, bias[l*4]);
    float acc1 = fmaf(sv.y, dd, bias[l*4+1]);
    float acc2 = fmaf(sv.z, dd, bias[l*4+2]);
    float acc3 = fmaf(sv.w, dd, bias[l*4+3]);
    for (int p = beg; p < end; p++){
        int s = ei[g_adj[p]];
        float nm = g_dinv[s] * di;
        float4 xv = *(const float4*)(g_xw + (size_t)s*64 + l*4);
        acc0 = fmaf(xv.x, nm, acc0);
        acc1 = fmaf(xv.y, nm, acc1);
        acc2 = fmaf(xv.z, nm, acc2);
        acc3 = fmaf(xv.w, nm, acc3);
    }
    acc0 = acc0 > 0.f ? acc0 : 0.01f*acc0;
    acc1 = acc1 > 0.f ? acc1 : 0.01f*acc1;
    acc2 = acc2 > 0.f ? acc2 : 0.01f*acc2;
    acc3 = acc3 > 0.f ? acc3 : 0.01f*acc3;
    *(float4*)(outp + (size_t)n*64 + l*4) = make_float4(acc0, acc1, acc2, acc3);
}

// ---- classifier layers 2+3 ----
__global__ void cls23_kernel(const float* __restrict__ W2, const float* __restrict__ b2,
                             const float* __restrict__ W3, const float* __restrict__ b3,
                             float* __restrict__ out){
    __shared__ float sW2[32*16], sW3[16*4], sb2[16], sb3[4];
    for (int i = threadIdx.x; i < 512; i += 256) sW2[i] = W2[i];
    for (int i = threadIdx.x; i < 64;  i += 256) sW3[i] = W3[i];
    if (threadIdx.x < 16) sb2[threadIdx.x] = b2[threadIdx.x];
    if (threadIdx.x < 4)  sb3[threadIdx.x] = b3[threadIdx.x];
    __syncthreads();
    int n = blockIdx.x * blockDim.x + threadIdx.x;
    if (n >= NN) return;
    float h2[16];
#pragma unroll
    for (int j = 0; j < 16; j++) h2[j] = sb2[j];
#pragma unroll
    for (int q = 0; q < 8; q++){
        float4 hv = *(const float4*)(g_h1 + (size_t)n*32 + q*4);
        float hh[4] = {hv.x, hv.y, hv.z, hv.w};
#pragma unroll
        for (int kk = 0; kk < 4; kk++)
#pragma unroll
            for (int j = 0; j < 16; j++) h2[j] = fmaf(hh[kk], sW2[(q*4+kk)*16 + j], h2[j]);
    }
#pragma unroll
    for (int j = 0; j < 16; j++) h2[j] = h2[j] > 0.f ? h2[j] : 0.01f*h2[j];
    float o[4] = {sb3[0], sb3[1], sb3[2], sb3[3]};
#pragma unroll
    for (int k = 0; k < 16; k++)
#pragma unroll
        for (int j = 0; j < 4; j++) o[j] = fmaf(h2[k], sW3[k*4 + j], o[j]);
    *(float4*)(out + (size_t)n*4) = make_float4(o[0], o[1], o[2], o[3]);
}

extern "C" void kernel_launch(void* const* d_in, const int* in_sizes, int n_in,
                              void* d_out, int out_size)
{
    const float* x    = (const float*)d_in[0];
    const float* eseq = (const float*)d_in[1];
    const float* nseq = (const float*)d_in[2];
    const float* Wih  = (const float*)d_in[3];
    const float* Whh  = (const float*)d_in[4];
    const float* lb   = (const float*)d_in[5];
    const float* dW   = (const float*)d_in[6];
    const float* dbv  = (const float*)d_in[7];
    const float* g1W  = (const float*)d_in[8];
    const float* g1att= (const float*)d_in[9];
    const float* g1b  = (const float*)d_in[10];
    const float* g2W  = (const float*)d_in[11];
    const float* g2att= (const float*)d_in[12];
    const float* g2b  = (const float*)d_in[13];
    const float* n1W  = (const float*)d_in[14];
    const float* n1b  = (const float*)d_in[15];
    const float* n2W  = (const float*)d_in[16];
    const float* n2b  = (const float*)d_in[17];
    const float* c1W  = (const float*)d_in[18];
    const float* c1b  = (const float*)d_in[19];
    const float* c2W  = (const float*)d_in[20];
    const float* c2b  = (const float*)d_in[21];
    const float* c3W  = (const float*)d_in[22];
    const float* c3b  = (const float*)d_in[23];
    const int*   ei   = (const int*)d_in[24];
    const int*   elen = (const int*)d_in[25];
    const int*   nlen = (const int*)d_in[26];

    float* out  = (float*)d_out;
    float* xgcn = out + (size_t)NN*4;
    float* xgat = xgcn + (size_t)NN*64;

    float *p_xin, *p_xh, *p_gat1, *p_xw, *p_gcn1, *p_h1;
    __nv_bfloat16 *bh1,*bl1,*bh2,*bl2,*bn1,*bn1l,*bn2,*bn2l,*bc1,*bc1l;
    cudaGetSymbolAddress((void**)&p_xin,  g_xin);
    cudaGetSymbolAddress((void**)&p_xh,   g_xh);
    cudaGetSymbolAddress((void**)&p_gat1, g_gat1);
    cudaGetSymbolAddress((void**)&p_xw,   g_xw);
    cudaGetSymbolAddress((void**)&p_gcn1, g_gcn1);
    cudaGetSymbolAddress((void**)&p_h1,   g_h1);
    cudaGetSymbolAddress((void**)&bh1,  g_bh1);  cudaGetSymbolAddress((void**)&bl1,  g_bl1);
    cudaGetSymbolAddress((void**)&bh2,  g_bh2);  cudaGetSymbolAddress((void**)&bl2,  g_bl2);
    cudaGetSymbolAddress((void**)&bn1,  g_bn1);  cudaGetSymbolAddress((void**)&bn1l, g_bn1l);
    cudaGetSymbolAddress((void**)&bn2,  g_bn2);  cudaGetSymbolAddress((void**)&bn2l, g_bn2l);
    cudaGetSymbolAddress((void**)&bc1,  g_bc1);  cudaGetSymbolAddress((void**)&bc1l, g_bc1l);

    static cudaStream_t s1 = nullptr, s2 = nullptr;
    static cudaEvent_t evRoot = nullptr, evEsc = nullptr, evXin = nullptr,
                       evGcn = nullptr, evCsr = nullptr;
    if (!s1){
        cudaStreamCreateWithFlags(&s1, cudaStreamNonBlocking);
        cudaStreamCreateWithFlags(&s2, cudaStreamNonBlocking);
        cudaEventCreateWithFlags(&evRoot, cudaEventDisableTiming);
        cudaEventCreateWithFlags(&evEsc,  cudaEventDisableTiming);
        cudaEventCreateWithFlags(&evXin,  cudaEventDisableTiming);
        cudaEventCreateWithFlags(&evGcn,  cudaEventDisableTiming);
        cudaEventCreateWithFlags(&evCsr,  cudaEventDisableTiming);
    }

    auto cdiv = [](int a, int b){ return (a + b - 1) / b; };
    cudaStream_t s0 = 0;
    const int NBLK = cdiv(NN, 256);

    cudaEventRecord(evRoot, s0);
    cudaStreamWaitEvent(s1, evRoot, 0);
    cudaStreamWaitEvent(s2, evRoot, 0);

    // ---- s1: edge LSTM -> esc ----
    lstm_kernel<<<2048, 256, 0, s1>>>(eseq, elen, Wih, Whh, lb, dW, dbv, EE, 1);
    cudaEventRecord(evEsc, s1);

    // ---- s2: CSR build + GCN/cls weight conversion ----
    zerocnt_kernel<<<NBLK, 256, 0, s2>>>();
    count_kernel<<<cdiv(EE,256), 256, 0, s2>>>(ei);
    scan1_kernel<<<NBLK, 256, 0, s2>>>();
    scan2_kernel<<<1, 256, 0, s2>>>(NBLK);
    scan3_kernel<<<NBLK, 256, 0, s2>>>();
    fillAdj_kernel<<<cdiv(EE,256), 256, 0, s2>>>(ei);
    cudaEventRecord(evCsr, s2);
    convw_kernel<<<cdiv(256*64,256),256,0,s2>>>(n1W, bn1, bn1l, 256, 64);
    convw_kernel<<<cdiv(64*64,256),256,0,s2>>>(n2W, bn2, bn2l, 64, 64);
    convw_kernel<<<cdiv(320*32,256),256,0,s2>>>(c1W, bc1, bc1l, 320, 32);

    // ---- s0: GAT weight conversion + node features ----
    convw_kernel<<<cdiv(256*64,256),256,0,s0>>>(g1W, bh1, bl1, 256, 64);
    convw_kernel<<<cdiv(64*64,256),256,0,s0>>>(g2W, bh2, bl2, 64, 64);
    lstm_kernel<<<512, 256, 0, s0>>>(nseq, nlen, Wih, Whh, lb, dW, dbv, NN, 0);
    copy_x_kernel<<<cdiv(NN*60,256), 256, 0, s0>>>(x);
    cudaEventRecord(evXin, s0);

    // ---- s0: GAT chain ----
    gemm_tc_kernel<64><<<cdiv(NN,128),256,0,s0>>>(p_xin,256,1<<30,nullptr,0, bh1,bl1, nullptr, p_xh, NN, 256, 0);
    alpha_kernel<<<cdiv(NN*8,256),256,0,s0>>>(g1att, 8);
    cudaStreamWaitEvent(s0, evCsr, 0);
    cudaStreamWaitEvent(s0, evEsc, 0);
    gatAgg_kernel<<<cdiv(NN*16,256),256,0,s0>>>(ei, g1b, p_gat1, 8, 0);
    gemm_tc_kernel<64><<<cdiv(NN,128),256,0,s0>>>(p_gat1,64,1<<30,nullptr,0, bh2,bl2, nullptr, p_xh, NN, 64, 0);
    alpha_kernel<<<cdiv(NN,256),256,0,s0>>>(g2att, 1);
    gatAgg_kernel<<<cdiv(NN*16,256),256,0,s0>>>(ei, g2b, xgat, 1, 1);

    // ---- s2: GCN chain ----
    cudaStreamWaitEvent(s2, evXin, 0);
    gemm_tc_kernel<64><<<cdiv(NN,128),256,0,s2>>>(p_xin,256,1<<30,nullptr,0, bn1,bn1l, nullptr, p_xw, NN, 256, 0);
    gcnAgg_kernel<<<cdiv(NN*16,256),256,0,s2>>>(ei, n1b, p_gcn1);
    gemm_tc_kernel<64><<<cdiv(NN,128),256,0,s2>>>(p_gcn1,64,1<<30,nullptr,0, bn2,bn2l, nullptr, p_xw, NN, 64, 0);
    gcnAgg_kernel<<<cdiv(NN*16,256),256,0,s2>>>(ei, n2b, xgcn);
    cudaEventRecord(evGcn, s2);

    // ---- join + classifier ----
    cudaStreamWaitEvent(s0, evGcn, 0);
    gemm_tc_kernel<32><<<cdiv(NN,128),256,0,s0>>>(p_xin,256,256, xgcn,64, bc1,bc1l, c1b, p_h1, NN, 320, 1);
    cls23_kernel<<<cdiv(NN,256),256,0,s0>>>(c2W, c2b, c3W, c3b, out);
}

// round 16
// speedup vs baseline: 1.6884x; 1.0298x over previous
#include <cuda_runtime.h>
#include <cuda_bf16.h>
#include <math.h>

#define NN 50000
#define EE 400000
typedef unsigned long long u64;
typedef unsigned int u32;

__device__ float g_xin [NN*256];
__device__ float g_esc [EE];
__device__ float g_xh  [NN*64];
__device__ float g_alpha[NN*8];
__device__ float g_gat1[NN*64];
__device__ float g_xw  [NN*64];
__device__ float g_gcn1[NN*64];
__device__ float g_dinv[NN];
__device__ float g_h1  [NN*32];
// CSR
__device__ int g_cnt[NN];
__device__ int g_off[NN+1];
__device__ int g_blk[256];
__device__ int g_adj[EE];
__device__ int g_srcCSR[EE];
__device__ float g_escCSR[EE];
__device__ float g_nrmCSR[EE];
__device__ float g_ea[EE*8];
// bf16 hi/lo transposed weight scratch
__device__ __nv_bfloat16 g_bh1[64*256], g_bl1[64*256];
__device__ __nv_bfloat16 g_bh2[64*64],  g_bl2[64*64];
__device__ __nv_bfloat16 g_bn1[64*256], g_bn1l[64*256];
__device__ __nv_bfloat16 g_bn2[64*64],  g_bn2l[64*64];
__device__ __nv_bfloat16 g_bc1[32*320], g_bc1l[32*320];

__device__ __forceinline__ float tanha(float x){
    float y; asm("tanh.approx.f32 %0, %1;" : "=f"(y) : "f"(x)); return y;
}
__device__ __forceinline__ float sigm(float x){ return fmaf(tanha(0.5f*x), 0.5f, 0.5f); }
__device__ __forceinline__ u64 pack2(float x, float y){
    u64 r; asm("mov.b64 %0, {%1,%2};" : "=l"(r) : "f"(x), "f"(y)); return r;
}
__device__ __forceinline__ u64 ffma2(u64 a, u64 b, u64 c){
    u64 d; asm("fma.rn.f32x2 %0, %1, %2, %3;" : "=l"(d) : "l"(a), "l"(b), "l"(c)); return d;
}
__device__ __forceinline__ float2 unpack2(u64 v){
    float2 f; asm("mov.b64 {%0,%1}, %2;" : "=f"(f.x), "=f"(f.y) : "l"(v)); return f;
}
__device__ __forceinline__ void mma16816(float* c, const u32* a, const u32* b){
    asm volatile("mma.sync.aligned.m16n8k16.row.col.f32.bf16.bf16.f32 "
        "{%0,%1,%2,%3}, {%4,%5,%6,%7}, {%8,%9}, {%0,%1,%2,%3};"
        : "+f"(c[0]), "+f"(c[1]), "+f"(c[2]), "+f"(c[3])
        : "r"(a[0]), "r"(a[1]), "r"(a[2]), "r"(a[3]), "r"(b[0]), "r"(b[1]));
}
__device__ __forceinline__ void split2(float2 v, u32& hi, u32& lo){
    __nv_bfloat162 h = __floats2bfloat162_rn(v.x, v.y);
    float rx = v.x - __bfloat162float(__low2bfloat16(h));
    float ry = v.y - __bfloat162float(__high2bfloat16(h));
    __nv_bfloat162 l = __floats2bfloat162_rn(rx, ry);
    hi = *(u32*)&h; lo = *(u32*)&l;
}

// ---- LSTM: 16 lanes per element, smem h-broadcast ----
__global__ __launch_bounds__(256, 2) void lstm_kernel(
    const float* __restrict__ seq, const int* __restrict__ lens,
    const float* __restrict__ Wih, const float* __restrict__ Whh,
    const float* __restrict__ bvec, const float* __restrict__ dnnW,
    const float* __restrict__ dnnb, int B, int mode)
{
    __shared__ float shh[8][2][2][16];
    __shared__ float sxx[8][2][32];
    int tid = threadIdx.x;
    int w = tid >> 5, lane = tid & 31;
    int grp = lane >> 4, u = lane & 15;
    int gid = (blockIdx.x * blockDim.x + tid) >> 4;
    int ngroups = (gridDim.x * blockDim.x) >> 4;

    u64 wif[16], wgo[16];
#pragma unroll
    for (int j = 0; j < 16; j++){
        wif[j] = pack2(Whh[u*16 + j],      Whh[(16+u)*16 + j]);
        wgo[j] = pack2(Whh[(32+u)*16 + j], Whh[(48+u)*16 + j]);
    }
    u64 wi0if = pack2(Wih[u*2],        Wih[(16+u)*2]);
    u64 wi1if = pack2(Wih[u*2+1],      Wih[(16+u)*2+1]);
    u64 wi0go = pack2(Wih[(32+u)*2],   Wih[(48+u)*2]);
    u64 wi1go = pack2(Wih[(32+u)*2+1], Wih[(48+u)*2+1]);
    u64 bif   = pack2(bvec[u],    bvec[16+u]);
    u64 bgo   = pack2(bvec[32+u], bvec[48+u]);
    float dw  = (mode == 1) ? dnnW[u] : 0.f;
    float dbv = (mode == 1) ? dnnb[0] : 0.f;

    for (int e = gid; e < B; e += ngroups){
        float2 v = ((const float2*)seq)[(size_t)e*16 + u];
        int L = lens[e];
        int Lo = __shfl_xor_sync(0xffffffffu, L, 16);
        int Lm = L > Lo ? L : Lo;
        sxx[w][grp][2*u]   = v.x;
        sxx[w][grp][2*u+1] = v.y;
        shh[w][0][grp][u]  = 0.f;
        __syncwarp();

        float h = 0.f, c = 0.f;
        for (int t = 0; t < Lm; t++){
            int rb = t & 1;
            float2 xv = *(float2*)&sxx[w][grp][2*t];
            u64 x0p = pack2(xv.x, xv.x), x1p = pack2(xv.y, xv.y);
            u64 gif = ffma2(x1p, wi1if, ffma2(x0p, wi0if, bif));
            u64 ggo = ffma2(x1p, wi1go, ffma2(x0p, wi0go, bgo));
            float4 H0 = *(float4*)&shh[w][rb][grp][0];
            float4 H1 = *(float4*)&shh[w][rb][grp][4];
            float4 H2 = *(float4*)&shh[w][rb][grp][8];
            float4 H3 = *(float4*)&shh[w][rb][grp][12];
            float hj[16] = {H0.x,H0.y,H0.z,H0.w, H1.x,H1.y,H1.z,H1.w,
                            H2.x,H2.y,H2.z,H2.w, H3.x,H3.y,H3.z,H3.w};
#pragma unroll
            for (int j = 0; j < 16; j++){
                u64 hp = pack2(hj[j], hj[j]);
                gif = ffma2(hp, wif[j], gif);
                ggo = ffma2(hp, wgo[j], ggo);
            }
            float2 gif2 = unpack2(gif), ggo2 = unpack2(ggo);
            if (t < L){
                c = fmaf(sigm(gif2.y), c, sigm(gif2.x) * tanha(ggo2.x));
                h = sigm(ggo2.y) * tanha(c);
            }
            shh[w][rb^1][grp][u] = h;
            __syncwarp();
        }

        if (mode == 0){
            g_xin[(size_t)e*256 + 240 + u] = h;
        } else {
            float val = h * dw;
#pragma unroll
            for (int off = 8; off; off >>= 1)
                val += __shfl_xor_sync(0xffffffffu, val, off, 16);
            if (u == 0) g_esc[e] = val + dbv;
        }
        __syncwarp();
    }
}

__global__ void copy_x_kernel(const float* __restrict__ x){
    int i = blockIdx.x * blockDim.x + threadIdx.x;
    if (i >= NN*60) return;
    int r = i / 60, cq = i % 60;
    ((float4*)g_xin)[r*64 + cq] = ((const float4*)x)[i];
}

// ---- weight split + transpose ----
__global__ void convw_kernel(const float* __restrict__ W, __nv_bfloat16* __restrict__ hiT,
                             __nv_bfloat16* __restrict__ loT, int K, int N){
    int i = blockIdx.x * blockDim.x + threadIdx.x;
    if (i >= K*N) return;
    int k = i / N, n = i - k*N;
    float v = W[i];
    __nv_bfloat16 h = __float2bfloat16(v);
    hiT[n*K + k] = h;
    loT[n*K + k] = __float2bfloat16(v - __bfloat162float(h));
}

// ---- CSR build ----
__global__ void zerocnt_kernel(){
    int i = blockIdx.x * blockDim.x + threadIdx.x;
    if (i < NN) g_cnt[i] = 0;
}
__global__ void count_kernel(const int* __restrict__ ei){
    int e = blockIdx.x * blockDim.x + threadIdx.x;
    if (e < EE) atomicAdd(&g_cnt[ei[EE+e]], 1);
}
__device__ __forceinline__ int blockScanIncl(int v, int tid, int* wt){
    int lane = tid & 31, w = tid >> 5;
    for (int o = 1; o < 32; o <<= 1){
        int u = __shfl_up_sync(0xffffffffu, v, o);
        if (lane >= o) v += u;
    }
    if (lane == 31) wt[w] = v;
    __syncthreads();
    if (w == 0){
        int s = (lane < 8) ? wt[lane] : 0;
        for (int o = 1; o < 8; o <<= 1){
            int u = __shfl_up_sync(0xffffffffu, s, o);
            if (lane >= o) s += u;
        }
        if (lane < 8) wt[lane] = s;
    }
    __syncthreads();
    if (w > 0) v += wt[w-1];
    return v;
}
__global__ void scan1_kernel(){
    __shared__ int wt[8];
    int tid = threadIdx.x;
    int i = blockIdx.x * 256 + tid;
    int c = (i < NN) ? g_cnt[i] : 0;
    int incl = blockScanIncl(c, tid, wt);
    if (i < NN){
        g_off[i] = incl - c;
        g_dinv[i] = rsqrtf((float)c + 1.f);
        g_cnt[i] = 0;
    }
    if (tid == 255) g_blk[blockIdx.x] = incl;
}
__global__ void scan2_kernel(int nblk){
    __shared__ int wt[8];
    int tid = threadIdx.x;
    int v = (tid < nblk) ? g_blk[tid] : 0;
    int incl = blockScanIncl(v, tid, wt);
    if (tid < nblk) g_blk[tid] = incl - v;
}
__global__ void scan3_kernel(){
    int tid = threadIdx.x;
    int i = blockIdx.x * 256 + tid;
    if (i < NN) g_off[i] += g_blk[blockIdx.x];
    if (i == 0) g_off[NN] = EE;
}
__global__ void fillAdj_kernel(const int* __restrict__ ei){
    int e = blockIdx.x * blockDim.x + threadIdx.x;
    if (e >= EE) return;
    int s = ei[e], d = ei[EE+e];
    int pos = g_off[d] + atomicAdd(&g_cnt[d], 1);
    g_adj[pos] = e;
    g_srcCSR[pos] = s;
}
// ---- CSR-ordered edge data prep (edge-parallel, high MLP) ----
__global__ void escCSR_kernel(){
    int p = blockIdx.x * blockDim.x + threadIdx.x;
    if (p < EE) g_escCSR[p] = g_esc[g_adj[p]];
}
__global__ void nrmCSR_kernel(){
    int p = blockIdx.x * blockDim.x + threadIdx.x;
    if (p < EE) g_nrmCSR[p] = g_dinv[g_srcCSR[p]];
}
__global__ void eaPrep_kernel(int H){
    int p = blockIdx.x * blockDim.x + threadIdx.x;
    if (p >= EE) return;
    int s = g_srcCSR[p];
    if (H == 8){
        float4 a0 = *(const float4*)&g_alpha[s*8];
        float4 a1 = *(const float4*)&g_alpha[s*8+4];
        float v[8] = {a0.x,a0.y,a0.z,a0.w,a1.x,a1.y,a1.z,a1.w};
#pragma unroll
        for (int h = 0; h < 8; h++){
            float a = v[h];
            a = a > 0.f ? a : 0.2f*a;
            v[h] = __expf(a);
        }
        *(float4*)&g_ea[p*8]   = make_float4(v[0],v[1],v[2],v[3]);
        *(float4*)&g_ea[p*8+4] = make_float4(v[4],v[5],v[6],v[7]);
    } else {
        float a = g_alpha[s];
        a = a > 0.f ? a : 0.2f*a;
        g_ea[p] = __expf(a);
    }
}

// ---- tensor-core GEMM ----
template<int N>
__global__ __launch_bounds__(256) void gemm_tc_kernel(
    const float* __restrict__ A, int lda, int K1,
    const float* __restrict__ A2, int lda2,
    const __nv_bfloat16* __restrict__ BhT, const __nv_bfloat16* __restrict__ BlT,
    const float* __restrict__ bias, float* __restrict__ Out,
    int M, int K, int act)
{
    constexpr int NT = N/8;
    int tid = threadIdx.x;
    int w = tid >> 5, lane = tid & 31;
    int gr = lane >> 2, t = lane & 3;
    int rowbase = blockIdx.x*128 + w*16;
    int r0 = rowbase + gr, r1 = r0 + 8;
    int r0c = r0 < M ? r0 : M-1;
    int r1c = r1 < M ? r1 : M-1;
    float acc[NT][4];
#pragma unroll
    for (int i = 0; i < NT; i++){ acc[i][0]=acc[i][1]=acc[i][2]=acc[i][3]=0.f; }

    for (int k = 0; k < K; k += 16){
        const float *p0, *p1;
        if (k < K1){ p0 = A + (size_t)r0c*lda + k;         p1 = A + (size_t)r1c*lda + k; }
        else       { p0 = A2 + (size_t)r0c*lda2 + (k-K1);  p1 = A2 + (size_t)r1c*lda2 + (k-K1); }
        float2 x00 = *(const float2*)(p0 + 2*t);
        float2 x02 = *(const float2*)(p0 + 2*t + 8);
        float2 x10 = *(const float2*)(p1 + 2*t);
        float2 x12 = *(const float2*)(p1 + 2*t + 8);
        u32 ah[4], al[4];
        split2(x00, ah[0], al[0]);
        split2(x10, ah[1], al[1]);
        split2(x02, ah[2], al[2]);
        split2(x12, ah[3], al[3]);
#pragma unroll
        for (int nt = 0; nt < NT; nt++){
            int n = nt*8 + gr;
            u32 bh[2], bl[2];
            bh[0] = *(const u32*)(BhT + n*K + k + 2*t);
            bh[1] = *(const u32*)(BhT + n*K + k + 8 + 2*t);
            bl[0] = *(const u32*)(BlT + n*K + k + 2*t);
            bl[1] = *(const u32*)(BlT + n*K + k + 8 + 2*t);
            mma16816(acc[nt], ah, bh);
            mma16816(acc[nt], ah, bl);
            mma16816(acc[nt], al, bh);
        }
    }
#pragma unroll
    for (int nt = 0; nt < NT; nt++){
        int c = nt*8 + 2*t;
        float b0 = bias ? bias[c] : 0.f, b1 = bias ? bias[c+1] : 0.f;
        float v0 = acc[nt][0]+b0, v1 = acc[nt][1]+b1;
        float v2 = acc[nt][2]+b0, v3 = acc[nt][3]+b1;
        if (act){
            v0 = v0>0.f?v0:0.01f*v0; v1 = v1>0.f?v1:0.01f*v1;
            v2 = v2>0.f?v2:0.01f*v2; v3 = v3>0.f?v3:0.01f*v3;
        }
        if (r0 < M) *(float2*)(Out + (size_t)r0*N + c) = make_float2(v0, v1);
        if (r1 < M) *(float2*)(Out + (size_t)r1*N + c) = make_float2(v2, v3);
    }
}

// ---- GAT alpha ----
__global__ void alpha_kernel(const float* __restrict__ att, int H){
    int i = blockIdx.x * blockDim.x + threadIdx.x;
    if (i >= NN*H) return;
    int n = i / H, h = i - n*H;
    int C = 64 / H;
    const float* xr = g_xh + (size_t)n*64 + h*C;
    const float* ar = att + h*C;
    float s = 0.f;
    for (int c = 0; c < C; c++) s = fmaf(xr[c], ar[c], s);
    g_alpha[i] = s;
}

// ---- GAT aggregate: sequential ea/esc/src + 4-way batched xh gather ----
__global__ void gatAgg_kernel(const float* __restrict__ bias,
                              float* __restrict__ outp, int H, int clean){
    int t = blockIdx.x * blockDim.x + threadIdx.x;
    int n = t >> 4;
    if (n >= NN) return;
    int l = t & 15;
    int h = (l*H) >> 4;
    int beg = g_off[n], end = g_off[n+1];

    float sum = 0.f;
    for (int p = beg; p < end; p++) sum += g_ea[p*H + h];
    float rinv = (end > beg) ? __fdividef(1.f, sum) : 0.f;

    float4 res = *(const float4*)(g_xh + (size_t)n*64 + l*4);
    float acc0 = res.x + bias[l*4], acc1 = res.y + bias[l*4+1];
    float acc2 = res.z + bias[l*4+2], acc3 = res.w + bias[l*4+3];

    int p = beg;
    for (; p + 4 <= end; p += 4){
        int s0 = g_srcCSR[p],   s1 = g_srcCSR[p+1];
        int s2 = g_srcCSR[p+2], s3 = g_srcCSR[p+3];
        float c0 = fmaf(g_ea[(p  )*H + h], rinv, g_escCSR[p  ]);
        float c1 = fmaf(g_ea[(p+1)*H + h], rinv, g_escCSR[p+1]);
        float c2 = fmaf(g_ea[(p+2)*H + h], rinv, g_escCSR[p+2]);
        float c3 = fmaf(g_ea[(p+3)*H + h], rinv, g_escCSR[p+3]);
        float4 v0 = *(const float4*)(g_xh + (size_t)s0*64 + l*4);
        float4 v1 = *(const float4*)(g_xh + (size_t)s1*64 + l*4);
        float4 v2 = *(const float4*)(g_xh + (size_t)s2*64 + l*4);
        float4 v3 = *(const float4*)(g_xh + (size_t)s3*64 + l*4);
        acc0 = fmaf(v0.x,c0, fmaf(v1.x,c1, fmaf(v2.x,c2, fmaf(v3.x,c3, acc0))));
        acc1 = fmaf(v0.y,c0, fmaf(v1.y,c1, fmaf(v2.y,c2, fmaf(v3.y,c3, acc1))));
        acc2 = fmaf(v0.z,c0, fmaf(v1.z,c1, fmaf(v2.z,c2, fmaf(v3.z,c3, acc2))));
        acc3 = fmaf(v0.w,c0, fmaf(v1.w,c1, fmaf(v2.w,c2, fmaf(v3.w,c3, acc3))));
    }
    for (; p < end; p++){
        int s = g_srcCSR[p];
        float cf = fmaf(g_ea[p*H + h], rinv, g_escCSR[p]);
        float4 xv = *(const float4*)(g_xh + (size_t)s*64 + l*4);
        acc0 = fmaf(xv.x, cf, acc0);
        acc1 = fmaf(xv.y, cf, acc1);
        acc2 = fmaf(xv.z, cf, acc2);
        acc3 = fmaf(xv.w, cf, acc3);
    }
    if (clean){
        if (!isfinite(acc0)) acc0 = 0.f;
        if (!isfinite(acc1)) acc1 = 0.f;
        if (!isfinite(acc2)) acc2 = 0.f;
        if (!isfinite(acc3)) acc3 = 0.f;
    }
    *(float4*)(outp + (size_t)n*64 + l*4) = make_float4(acc0, acc1, acc2, acc3);
}

// ---- GCN aggregate: sequential nrm/src + 4-way batched xw gather ----
__global__ void gcnAgg_kernel(const float* __restrict__ bias,
                              float* __restrict__ outp){
    int t = blockIdx.x * blockDim.x + threadIdx.x;
    int n = t >> 4;
    if (n >= NN) return;
    int l = t & 15;
    int beg = g_off[n], end = g_off[n+1];
    float di = g_dinv[n];

    float4 sv = *(const float4*)(g_xw + (size_t)n*64 + l*4);
    float dd = di * di;
    float acc0 = fmaf(sv.x, dd, bias[l*4]);
    float acc1 = fmaf(sv.y, dd, bias[l*4+1]);
    float acc2 = fmaf(sv.z, dd, bias[l*4+2]);
    float acc3 = fmaf(sv.w, dd, bias[l*4+3]);

    int p = beg;
    for (; p + 4 <= end; p += 4){
        int s0 = g_srcCSR[p],   s1 = g_srcCSR[p+1];
        int s2 = g_srcCSR[p+2], s3 = g_srcCSR[p+3];
        float c0 = g_nrmCSR[p]   * di;
        float c1 = g_nrmCSR[p+1] * di;
        float c2 = g_nrmCSR[p+2] * di;
        float c3 = g_nrmCSR[p+3] * di;
        float4 v0 = *(const float4*)(g_xw + (size_t)s0*64 + l*4);
        float4 v1 = *(const float4*)(g_xw + (size_t)s1*64 + l*4);
        float4 v2 = *(const float4*)(g_xw + (size_t)s2*64 + l*4);
        float4 v3 = *(const float4*)(g_xw + (size_t)s3*64 + l*4);
        acc0 = fmaf(v0.x,c0, fmaf(v1.x,c1, fmaf(v2.x,c2, fmaf(v3.x,c3, acc0))));
        acc1 = fmaf(v0.y,c0, fmaf(v1.y,c1, fmaf(v2.y,c2, fmaf(v3.y,c3, acc1))));
        acc2 = fmaf(v0.z,c0, fmaf(v1.z,c1, fmaf(v2.z,c2, fmaf(v3.z,c3, acc2))));
        acc3 = fmaf(v0.w,c0, fmaf(v1.w,c1, fmaf(v2.w,c2, fmaf(v3.w,c3, acc3))));
    }
    for (; p < end; p++){
        int s = g_srcCSR[p];
        float nm = g_nrmCSR[p] * di;
        float4 xv = *(const float4*)(g_xw + (size_t)s*64 + l*4);
        acc0 = fmaf(xv.x, nm, acc0);
        acc1 = fmaf(xv.y, nm, acc1);
        acc2 = fmaf(xv.z, nm, acc2);
        acc3 = fmaf(xv.w, nm, acc3);
    }
    acc0 = acc0 > 0.f ? acc0 : 0.01f*acc0;
    acc1 = acc1 > 0.f ? acc1 : 0.01f*acc1;
    acc2 = acc2 > 0.f ? acc2 : 0.01f*acc2;
    acc3 = acc3 > 0.f ? acc3 : 0.01f*acc3;
    *(float4*)(outp + (size_t)n*64 + l*4) = make_float4(acc0, acc1, acc2, acc3);
}

// ---- classifier layers 2+3 ----
__global__ void cls23_kernel(const float* __restrict__ W2, const float* __restrict__ b2,
                             const float* __restrict__ W3, const float* __restrict__ b3,
                             float* __restrict__ out){
    __shared__ float sW2[32*16], sW3[16*4], sb2[16], sb3[4];
    for (int i = threadIdx.x; i < 512; i += 256) sW2[i] = W2[i];
    for (int i = threadIdx.x; i < 64;  i += 256) sW3[i] = W3[i];
    if (threadIdx.x < 16) sb2[threadIdx.x] = b2[threadIdx.x];
    if (threadIdx.x < 4)  sb3[threadIdx.x] = b3[threadIdx.x];
    __syncthreads();
    int n = blockIdx.x * blockDim.x + threadIdx.x;
    if (n >= NN) return;
    float h2[16];
#pragma unroll
    for (int j = 0; j < 16; j++) h2[j] = sb2[j];
#pragma unroll
    for (int q = 0; q < 8; q++){
        float4 hv = *(const float4*)(g_h1 + (size_t)n*32 + q*4);
        float hh[4] = {hv.x, hv.y, hv.z, hv.w};
#pragma unroll
        for (int kk = 0; kk < 4; kk++)
#pragma unroll
            for (int j = 0; j < 16; j++) h2[j] = fmaf(hh[kk], sW2[(q*4+kk)*16 + j], h2[j]);
    }
#pragma unroll
    for (int j = 0; j < 16; j++) h2[j] = h2[j] > 0.f ? h2[j] : 0.01f*h2[j];
    float o[4] = {sb3[0], sb3[1], sb3[2], sb3[3]};
#pragma unroll
    for (int k = 0; k < 16; k++)
#pragma unroll
        for (int j = 0; j < 4; j++) o[j] = fmaf(h2[k], sW3[k*4 + j], o[j]);
    *(float4*)(out + (size_t)n*4) = make_float4(o[0], o[1], o[2], o[3]);
}

extern "C" void kernel_launch(void* const* d_in, const int* in_sizes, int n_in,
                              void* d_out, int out_size)
{
    const float* x    = (const float*)d_in[0];
    const float* eseq = (const float*)d_in[1];
    const float* nseq = (const float*)d_in[2];
    const float* Wih  = (const float*)d_in[3];
    const float* Whh  = (const float*)d_in[4];
    const float* lb   = (const float*)d_in[5];
    const float* dW   = (const float*)d_in[6];
    const float* dbv  = (const float*)d_in[7];
    const float* g1W  = (const float*)d_in[8];
    const float* g1att= (const float*)d_in[9];
    const float* g1b  = (const float*)d_in[10];
    const float* g2W  = (const float*)d_in[11];
    const float* g2att= (const float*)d_in[12];
    const float* g2b  = (const float*)d_in[13];
    const float* n1W  = (const float*)d_in[14];
    const float* n1b  = (const float*)d_in[15];
    const float* n2W  = (const float*)d_in[16];
    const float* n2b  = (const float*)d_in[17];
    const float* c1W  = (const float*)d_in[18];
    const float* c1b  = (const float*)d_in[19];
    const float* c2W  = (const float*)d_in[20];
    const float* c2b  = (const float*)d_in[21];
    const float* c3W  = (const float*)d_in[22];
    const float* c3b  = (const float*)d_in[23];
    const int*   ei   = (const int*)d_in[24];
    const int*   elen = (const int*)d_in[25];
    const int*   nlen = (const int*)d_in[26];

    float* out  = (float*)d_out;
    float* xgcn = out + (size_t)NN*4;
    float* xgat = xgcn + (size_t)NN*64;

    float *p_xin, *p_xh, *p_gat1, *p_xw, *p_gcn1, *p_h1;
    __nv_bfloat16 *bh1,*bl1,*bh2,*bl2,*bn1,*bn1l,*bn2,*bn2l,*bc1,*bc1l;
    cudaGetSymbolAddress((void**)&p_xin,  g_xin);
    cudaGetSymbolAddress((void**)&p_xh,   g_xh);
    cudaGetSymbolAddress((void**)&p_gat1, g_gat1);
    cudaGetSymbolAddress((void**)&p_xw,   g_xw);
    cudaGetSymbolAddress((void**)&p_gcn1, g_gcn1);
    cudaGetSymbolAddress((void**)&p_h1,   g_h1);
    cudaGetSymbolAddress((void**)&bh1,  g_bh1);  cudaGetSymbolAddress((void**)&bl1,  g_bl1);
    cudaGetSymbolAddress((void**)&bh2,  g_bh2);  cudaGetSymbolAddress((void**)&bl2,  g_bl2);
    cudaGetSymbolAddress((void**)&bn1,  g_bn1);  cudaGetSymbolAddress((void**)&bn1l, g_bn1l);
    cudaGetSymbolAddress((void**)&bn2,  g_bn2);  cudaGetSymbolAddress((void**)&bn2l, g_bn2l);
    cudaGetSymbolAddress((void**)&bc1,  g_bc1);  cudaGetSymbolAddress((void**)&bc1l, g_bc1l);

    static cudaStream_t s1 = nullptr, s2 = nullptr;
    static cudaEvent_t evRoot = nullptr, evEsc = nullptr, evXin = nullptr,
                       evGcn = nullptr, evCsr = nullptr, evEscC = nullptr;
    if (!s1){
        cudaStreamCreateWithFlags(&s1, cudaStreamNonBlocking);
        cudaStreamCreateWithFlags(&s2, cudaStreamNonBlocking);
        cudaEventCreateWithFlags(&evRoot, cudaEventDisableTiming);
        cudaEventCreateWithFlags(&evEsc,  cudaEventDisableTiming);
        cudaEventCreateWithFlags(&evXin,  cudaEventDisableTiming);
        cudaEventCreateWithFlags(&evGcn,  cudaEventDisableTiming);
        cudaEventCreateWithFlags(&evCsr,  cudaEventDisableTiming);
        cudaEventCreateWithFlags(&evEscC, cudaEventDisableTiming);
    }

    auto cdiv = [](int a, int b){ return (a + b - 1) / b; };
    cudaStream_t s0 = 0;
    const int NBLK = cdiv(NN, 256);

    cudaEventRecord(evRoot, s0);
    cudaStreamWaitEvent(s1, evRoot, 0);
    cudaStreamWaitEvent(s2, evRoot, 0);

    // ---- s1: edge LSTM -> esc, then CSR-ordered esc ----
    lstm_kernel<<<2048, 256, 0, s1>>>(eseq, elen, Wih, Whh, lb, dW, dbv, EE, 1);
    cudaEventRecord(evEsc, s1);

    // ---- s2: CSR build + nrmCSR + GCN/cls weight conversion ----
    zerocnt_kernel<<<NBLK, 256, 0, s2>>>();
    count_kernel<<<cdiv(EE,256), 256, 0, s2>>>(ei);
    scan1_kernel<<<NBLK, 256, 0, s2>>>();
    scan2_kernel<<<1, 256, 0, s2>>>(NBLK);
    scan3_kernel<<<NBLK, 256, 0, s2>>>();
    fillAdj_kernel<<<cdiv(EE,256), 256, 0, s2>>>(ei);
    nrmCSR_kernel<<<cdiv(EE,256), 256, 0, s2>>>();
    cudaEventRecord(evCsr, s2);
    convw_kernel<<<cdiv(256*64,256),256,0,s2>>>(n1W, bn1, bn1l, 256, 64);
    convw_kernel<<<cdiv(64*64,256),256,0,s2>>>(n2W, bn2, bn2l, 64, 64);
    convw_kernel<<<cdiv(320*32,256),256,0,s2>>>(c1W, bc1, bc1l, 320, 32);

    // ---- s1 (cont): escCSR after esc + CSR ----
    cudaStreamWaitEvent(s1, evCsr, 0);
    escCSR_kernel<<<cdiv(EE,256), 256, 0, s1>>>();
    cudaEventRecord(evEscC, s1);

    // ---- s0: GAT weight conversion + node features ----
    convw_kernel<<<cdiv(256*64,256),256,0,s0>>>(g1W, bh1, bl1, 256, 64);
    convw_kernel<<<cdiv(64*64,256),256,0,s0>>>(g2W, bh2, bl2, 64, 64);
    lstm_kernel<<<512, 256, 0, s0>>>(nseq, nlen, Wih, Whh, lb, dW, dbv, NN, 0);
    copy_x_kernel<<<cdiv(NN*60,256), 256, 0, s0>>>(x);
    cudaEventRecord(evXin, s0);

    // ---- s0: GAT chain ----
    gemm_tc_kernel<64><<<cdiv(NN,128),256,0,s0>>>(p_xin,256,1<<30,nullptr,0, bh1,bl1, nullptr, p_xh, NN, 256, 0);
    alpha_kernel<<<cdiv(NN*8,256),256,0,s0>>>(g1att, 8);
    cudaStreamWaitEvent(s0, evCsr, 0);
    eaPrep_kernel<<<cdiv(EE,256),256,0,s0>>>(8);
    cudaStreamWaitEvent(s0, evEscC, 0);
    gatAgg_kernel<<<cdiv(NN*16,256),256,0,s0>>>(g1b, p_gat1, 8, 0);
    gemm_tc_kernel<64><<<cdiv(NN,128),256,0,s0>>>(p_gat1,64,1<<30,nullptr,0, bh2,bl2, nullptr, p_xh, NN, 64, 0);
    alpha_kernel<<<cdiv(NN,256),256,0,s0>>>(g2att, 1);
    eaPrep_kernel<<<cdiv(EE,256),256,0,s0>>>(1);
    gatAgg_kernel<<<cdiv(NN*16,256),256,0,s0>>>(g2b, xgat, 1, 1);

    // ---- s2: GCN chain ----
    cudaStreamWaitEvent(s2, evXin, 0);
    gemm_tc_kernel<64><<<cdiv(NN,128),256,0,s2>>>(p_xin,256,1<<30,nullptr,0, bn1,bn1l, nullptr, p_xw, NN, 256, 0);
    gcnAgg_kernel<<<cdiv(NN*16,256),256,0,s2>>>(n1b, p_gcn1);
    gemm_tc_kernel<64><<<cdiv(NN,128),256,0,s2>>>(p_gcn1,64,1<<30,nullptr,0, bn2,bn2l, nullptr, p_xw, NN, 64, 0);
    gcnAgg_kernel<<<cdiv(NN*16,256),256,0,s2>>>(n2b, xgcn);
    cudaEventRecord(evGcn, s2);

    // ---- join + classifier ----
    cudaStreamWaitEvent(s0, evGcn, 0);
    gemm_tc_kernel<32><<<cdiv(NN,128),256,0,s0>>>(p_xin,256,256, xgcn,64, bc1,bc1l, c1b, p_h1, NN, 320, 1);
    cls23_kernel<<<cdiv(NN,256),256,0,s0>>>(c2W, c2b, c3W, c3b, out);
}

// round 17
// speedup vs baseline: 1.6905x; 1.0013x over previous
#include <cuda_runtime.h>
#include <cuda_bf16.h>
#include <math.h>

#define NN 50000
#define EE 400000
typedef unsigned long long u64;
typedef unsigned int u32;

__device__ float g_nf  [NN*16];
__device__ float g_esc [EE];
__device__ float g_xh  [NN*64];
__device__ float g_alpha[NN*8];
__device__ float g_gat1[NN*64];
__device__ float g_xw  [NN*64];
__device__ float g_gcn1[NN*64];
__device__ float g_dinv[NN];
__device__ float g_h1  [NN*32];
// CSR
__device__ int g_cnt[NN];
__device__ int g_off[NN+1];
__device__ int g_blk[256];
__device__ int g_adj[EE];
__device__ int g_srcCSR[EE];
__device__ float g_escCSR[EE];
__device__ float g_nrmCSR[EE];
__device__ float g_ea[EE*8];
// bf16 hi/lo transposed weight scratch
__device__ __nv_bfloat16 g_bh1[64*256], g_bl1[64*256];
__device__ __nv_bfloat16 g_bh2[64*64],  g_bl2[64*64];
__device__ __nv_bfloat16 g_bn1[64*256], g_bn1l[64*256];
__device__ __nv_bfloat16 g_bn2[64*64],  g_bn2l[64*64];
__device__ __nv_bfloat16 g_bc1[32*320], g_bc1l[32*320];

__device__ __forceinline__ float tanha(float x){
    float y; asm("tanh.approx.f32 %0, %1;" : "=f"(y) : "f"(x)); return y;
}
__device__ __forceinline__ float sigm(float x){ return fmaf(tanha(0.5f*x), 0.5f, 0.5f); }
__device__ __forceinline__ u64 pack2(float x, float y){
    u64 r; asm("mov.b64 %0, {%1,%2};" : "=l"(r) : "f"(x), "f"(y)); return r;
}
__device__ __forceinline__ u64 ffma2(u64 a, u64 b, u64 c){
    u64 d; asm("fma.rn.f32x2 %0, %1, %2, %3;" : "=l"(d) : "l"(a), "l"(b), "l"(c)); return d;
}
__device__ __forceinline__ float2 unpack2(u64 v){
    float2 f; asm("mov.b64 {%0,%1}, %2;" : "=f"(f.x), "=f"(f.y) : "l"(v)); return f;
}
__device__ __forceinline__ void mma16816(float* c, const u32* a, const u32* b){
    asm volatile("mma.sync.aligned.m16n8k16.row.col.f32.bf16.bf16.f32 "
        "{%0,%1,%2,%3}, {%4,%5,%6,%7}, {%8,%9}, {%0,%1,%2,%3};"
        : "+f"(c[0]), "+f"(c[1]), "+f"(c[2]), "+f"(c[3])
        : "r"(a[0]), "r"(a[1]), "r"(a[2]), "r"(a[3]), "r"(b[0]), "r"(b[1]));
}
__device__ __forceinline__ void split2(float2 v, u32& hi, u32& lo){
    __nv_bfloat162 h = __floats2bfloat162_rn(v.x, v.y);
    float rx = v.x - __bfloat162float(__low2bfloat16(h));
    float ry = v.y - __bfloat162float(__high2bfloat16(h));
    __nv_bfloat162 l = __floats2bfloat162_rn(rx, ry);
    hi = *(u32*)&h; lo = *(u32*)&l;
}

// ---- LSTM: 16 lanes per element, smem h-broadcast ----
__global__ __launch_bounds__(256, 2) void lstm_kernel(
    const float* __restrict__ seq, const int* __restrict__ lens,
    const float* __restrict__ Wih, const float* __restrict__ Whh,
    const float* __restrict__ bvec, const float* __restrict__ dnnW,
    const float* __restrict__ dnnb, int B, int mode)
{
    __shared__ float shh[8][2][2][16];
    __shared__ float sxx[8][2][32];
    int tid = threadIdx.x;
    int w = tid >> 5, lane = tid & 31;
    int grp = lane >> 4, u = lane & 15;
    int gid = (blockIdx.x * blockDim.x + tid) >> 4;
    int ngroups = (gridDim.x * blockDim.x) >> 4;

    u64 wif[16], wgo[16];
#pragma unroll
    for (int j = 0; j < 16; j++){
        wif[j] = pack2(Whh[u*16 + j],      Whh[(16+u)*16 + j]);
        wgo[j] = pack2(Whh[(32+u)*16 + j], Whh[(48+u)*16 + j]);
    }
    u64 wi0if = pack2(Wih[u*2],        Wih[(16+u)*2]);
    u64 wi1if = pack2(Wih[u*2+1],      Wih[(16+u)*2+1]);
    u64 wi0go = pack2(Wih[(32+u)*2],   Wih[(48+u)*2]);
    u64 wi1go = pack2(Wih[(32+u)*2+1], Wih[(48+u)*2+1]);
    u64 bif   = pack2(bvec[u],    bvec[16+u]);
    u64 bgo   = pack2(bvec[32+u], bvec[48+u]);
    float dw  = (mode == 1) ? dnnW[u] : 0.f;
    float dbv = (mode == 1) ? dnnb[0] : 0.f;

    for (int e = gid; e < B; e += ngroups){
        float2 v = ((const float2*)seq)[(size_t)e*16 + u];
        int L = lens[e];
        int Lo = __shfl_xor_sync(0xffffffffu, L, 16);
        int Lm = L > Lo ? L : Lo;
        sxx[w][grp][2*u]   = v.x;
        sxx[w][grp][2*u+1] = v.y;
        shh[w][0][grp][u]  = 0.f;
        __syncwarp();

        float h = 0.f, c = 0.f;
        for (int t = 0; t < Lm; t++){
            int rb = t & 1;
            float2 xv = *(float2*)&sxx[w][grp][2*t];
            u64 x0p = pack2(xv.x, xv.x), x1p = pack2(xv.y, xv.y);
            u64 gif = ffma2(x1p, wi1if, ffma2(x0p, wi0if, bif));
            u64 ggo = ffma2(x1p, wi1go, ffma2(x0p, wi0go, bgo));
            float4 H0 = *(float4*)&shh[w][rb][grp][0];
            float4 H1 = *(float4*)&shh[w][rb][grp][4];
            float4 H2 = *(float4*)&shh[w][rb][grp][8];
            float4 H3 = *(float4*)&shh[w][rb][grp][12];
            float hj[16] = {H0.x,H0.y,H0.z,H0.w, H1.x,H1.y,H1.z,H1.w,
                            H2.x,H2.y,H2.z,H2.w, H3.x,H3.y,H3.z,H3.w};
#pragma unroll
            for (int j = 0; j < 16; j++){
                u64 hp = pack2(hj[j], hj[j]);
                gif = ffma2(hp, wif[j], gif);
                ggo = ffma2(hp, wgo[j], ggo);
            }
            float2 gif2 = unpack2(gif), ggo2 = unpack2(ggo);
            if (t < L){
                c = fmaf(sigm(gif2.y), c, sigm(gif2.x) * tanha(ggo2.x));
                h = sigm(ggo2.y) * tanha(c);
            }
            shh[w][rb^1][grp][u] = h;
            __syncwarp();
        }

        if (mode == 0){
            g_nf[(size_t)e*16 + u] = h;
        } else {
            float val = h * dw;
#pragma unroll
            for (int off = 8; off; off >>= 1)
                val += __shfl_xor_sync(0xffffffffu, val, off, 16);
            if (u == 0) g_esc[e] = val + dbv;
        }
        __syncwarp();
    }
}

// ---- all weight conversions in one kernel ----
__device__ __forceinline__ void convone(const float* __restrict__ W, int i, int K, int N,
                                        __nv_bfloat16* __restrict__ hiT,
                                        __nv_bfloat16* __restrict__ loT){
    int k = i / N, n = i - k*N;
    float v = W[i];
    __nv_bfloat16 h = __float2bfloat16(v);
    hiT[n*K + k] = h;
    loT[n*K + k] = __float2bfloat16(v - __bfloat162float(h));
}
__global__ void convw_all_kernel(const float* __restrict__ g1W, const float* __restrict__ g2W,
                                 const float* __restrict__ n1W, const float* __restrict__ n2W,
                                 const float* __restrict__ c1W){
    int i = blockIdx.x * blockDim.x + threadIdx.x;
    if (i < 16384)      convone(g1W, i,        256, 64, g_bh1, g_bl1);
    else if (i < 20480) convone(g2W, i-16384,   64, 64, g_bh2, g_bl2);
    else if (i < 36864) convone(n1W, i-20480,  256, 64, g_bn1, g_bn1l);
    else if (i < 40960) convone(n2W, i-36864,   64, 64, g_bn2, g_bn2l);
    else if (i < 51200) convone(c1W, i-40960,  320, 32, g_bc1, g_bc1l);
}

// ---- CSR build ----
__global__ void zerocnt_kernel(){
    int i = blockIdx.x * blockDim.x + threadIdx.x;
    if (i < NN) g_cnt[i] = 0;
}
__global__ void count_kernel(const int* __restrict__ ei){
    int e = blockIdx.x * blockDim.x + threadIdx.x;
    if (e < EE) atomicAdd(&g_cnt[ei[EE+e]], 1);
}
__device__ __forceinline__ int blockScanIncl(int v, int tid, int* wt){
    int lane = tid & 31, w = tid >> 5;
    for (int o = 1; o < 32; o <<= 1){
        int u = __shfl_up_sync(0xffffffffu, v, o);
        if (lane >= o) v += u;
    }
    if (lane == 31) wt[w] = v;
    __syncthreads();
    if (w == 0){
        int s = (lane < 8) ? wt[lane] : 0;
        for (int o = 1; o < 8; o <<= 1){
            int u = __shfl_up_sync(0xffffffffu, s, o);
            if (lane >= o) s += u;
        }
        if (lane < 8) wt[lane] = s;
    }
    __syncthreads();
    if (w > 0) v += wt[w-1];
    return v;
}
__global__ void scan1_kernel(){
    __shared__ int wt[8];
    int tid = threadIdx.x;
    int i = blockIdx.x * 256 + tid;
    int c = (i < NN) ? g_cnt[i] : 0;
    int incl = blockScanIncl(c, tid, wt);
    if (i < NN){
        g_off[i] = incl - c;
        g_dinv[i] = rsqrtf((float)c + 1.f);
        g_cnt[i] = 0;
    }
    if (tid == 255) g_blk[blockIdx.x] = incl;
}
__global__ void scan2_kernel(int nblk){
    __shared__ int wt[8];
    int tid = threadIdx.x;
    int v = (tid < nblk) ? g_blk[tid] : 0;
    int incl = blockScanIncl(v, tid, wt);
    if (tid < nblk) g_blk[tid] = incl - v;
}
__global__ void scan3_kernel(){
    int tid = threadIdx.x;
    int i = blockIdx.x * 256 + tid;
    if (i < NN) g_off[i] += g_blk[blockIdx.x];
    if (i == 0) g_off[NN] = EE;
}
__global__ void fillAdj_kernel(const int* __restrict__ ei){
    int e = blockIdx.x * blockDim.x + threadIdx.x;
    if (e >= EE) return;
    int s = ei[e], d = ei[EE+e];
    int pos = g_off[d] + atomicAdd(&g_cnt[d], 1);
    g_adj[pos] = e;
    g_srcCSR[pos] = s;
    g_nrmCSR[pos] = g_dinv[s];
}
// ---- CSR-ordered edge data prep ----
__global__ void escCSR_kernel(){
    int p = blockIdx.x * blockDim.x + threadIdx.x;
    if (p < EE) g_escCSR[p] = g_esc[g_adj[p]];
}
__global__ void eaPrep_kernel(int H){
    int p = blockIdx.x * blockDim.x + threadIdx.x;
    if (p >= EE) return;
    int s = g_srcCSR[p];
    if (H == 8){
        float4 a0 = *(const float4*)&g_alpha[s*8];
        float4 a1 = *(const float4*)&g_alpha[s*8+4];
        float v[8] = {a0.x,a0.y,a0.z,a0.w,a1.x,a1.y,a1.z,a1.w};
#pragma unroll
        for (int h = 0; h < 8; h++){
            float a = v[h];
            a = a > 0.f ? a : 0.2f*a;
            v[h] = __expf(a);
        }
        *(float4*)&g_ea[p*8]   = make_float4(v[0],v[1],v[2],v[3]);
        *(float4*)&g_ea[p*8+4] = make_float4(v[4],v[5],v[6],v[7]);
    } else {
        float a = g_alpha[s];
        a = a > 0.f ? a : 0.2f*a;
        g_ea[p] = __expf(a);
    }
}

// ---- A-fragment loader for 3-segment A ----
__device__ __forceinline__ const float* segptr(
    const float* __restrict__ A1, int lda1, int K1,
    const float* __restrict__ A2, int lda2, int K2,
    const float* __restrict__ A3, int lda3,
    int r, int k, int& kk)
{
    if (k < K1){ kk = k;      return A1 + (size_t)r*lda1; }
    if (k < K2){ kk = k - K1; return A2 + (size_t)r*lda2; }
    kk = k - K2; return A3 + (size_t)r*lda3;
}

// ---- tensor-core GEMM (3-segment A) ----
template<int N>
__global__ __launch_bounds__(256) void gemm_tc3_kernel(
    const float* __restrict__ A1, int lda1, int K1,
    const float* __restrict__ A2, int lda2, int K2,
    const float* __restrict__ A3, int lda3,
    const __nv_bfloat16* __restrict__ BhT, const __nv_bfloat16* __restrict__ BlT,
    const float* __restrict__ bias, float* __restrict__ Out,
    int M, int K, int act)
{
    constexpr int NT = N/8;
    int tid = threadIdx.x;
    int w = tid >> 5, lane = tid & 31;
    int gr = lane >> 2, t = lane & 3;
    int rowbase = blockIdx.x*128 + w*16;
    int r0 = rowbase + gr, r1 = r0 + 8;
    int r0c = r0 < M ? r0 : M-1;
    int r1c = r1 < M ? r1 : M-1;
    float acc[NT][4];
#pragma unroll
    for (int i = 0; i < NT; i++){ acc[i][0]=acc[i][1]=acc[i][2]=acc[i][3]=0.f; }

    for (int k = 0; k < K; k += 16){
        int kk0, kk1;
        const float* p0 = segptr(A1,lda1,K1, A2,lda2,K2, A3,lda3, r0c, k, kk0);
        const float* p1 = segptr(A1,lda1,K1, A2,lda2,K2, A3,lda3, r1c, k, kk1);
        float2 x00 = *(const float2*)(p0 + kk0 + 2*t);
        float2 x02 = *(const float2*)(p0 + kk0 + 2*t + 8);
        float2 x10 = *(const float2*)(p1 + kk1 + 2*t);
        float2 x12 = *(const float2*)(p1 + kk1 + 2*t + 8);
        u32 ah[4], al[4];
        split2(x00, ah[0], al[0]);
        split2(x10, ah[1], al[1]);
        split2(x02, ah[2], al[2]);
        split2(x12, ah[3], al[3]);
#pragma unroll
        for (int nt = 0; nt < NT; nt++){
            int n = nt*8 + gr;
            u32 bh[2], bl[2];
            bh[0] = *(const u32*)(BhT + n*K + k + 2*t);
            bh[1] = *(const u32*)(BhT + n*K + k + 8 + 2*t);
            bl[0] = *(const u32*)(BlT + n*K + k + 2*t);
            bl[1] = *(const u32*)(BlT + n*K + k + 8 + 2*t);
            mma16816(acc[nt], ah, bh);
            mma16816(acc[nt], ah, bl);
            mma16816(acc[nt], al, bh);
        }
    }
#pragma unroll
    for (int nt = 0; nt < NT; nt++){
        int c = nt*8 + 2*t;
        float b0 = bias ? bias[c] : 0.f, b1 = bias ? bias[c+1] : 0.f;
        float v0 = acc[nt][0]+b0, v1 = acc[nt][1]+b1;
        float v2 = acc[nt][2]+b0, v3 = acc[nt][3]+b1;
        if (act){
            v0 = v0>0.f?v0:0.01f*v0; v1 = v1>0.f?v1:0.01f*v1;
            v2 = v2>0.f?v2:0.01f*v2; v3 = v3>0.f?v3:0.01f*v3;
        }
        if (r0 < M) *(float2*)(Out + (size_t)r0*N + c) = make_float2(v0, v1);
        if (r1 < M) *(float2*)(Out + (size_t)r1*N + c) = make_float2(v2, v3);
    }
}

// ---- dual-B GEMM: one A stream, two outputs (GAT1 + GCN1) ----
__global__ __launch_bounds__(256) void gemm_dual_kernel(
    const float* __restrict__ A1, int lda1, int K1,
    const float* __restrict__ A2, int lda2,
    const __nv_bfloat16* __restrict__ BhA, const __nv_bfloat16* __restrict__ BlA,
    const __nv_bfloat16* __restrict__ BhB, const __nv_bfloat16* __restrict__ BlB,
    float* __restrict__ OutA, float* __restrict__ OutB, int M, int K)
{
    constexpr int NT = 8;
    int tid = threadIdx.x;
    int w = tid >> 5, lane = tid & 31;
    int gr = lane >> 2, t = lane & 3;
    int rowbase = blockIdx.x*128 + w*16;
    int r0 = rowbase + gr, r1 = r0 + 8;
    int r0c = r0 < M ? r0 : M-1;
    int r1c = r1 < M ? r1 : M-1;
    float accA[NT][4], accB[NT][4];
#pragma unroll
    for (int i = 0; i < NT; i++){
        accA[i][0]=accA[i][1]=accA[i][2]=accA[i][3]=0.f;
        accB[i][0]=accB[i][1]=accB[i][2]=accB[i][3]=0.f;
    }

    for (int k = 0; k < K; k += 16){
        const float *p0, *p1; int kk0, kk1;
        if (k < K1){ p0 = A1 + (size_t)r0c*lda1; kk0 = k; p1 = A1 + (size_t)r1c*lda1; kk1 = k; }
        else       { p0 = A2 + (size_t)r0c*lda2; kk0 = k-K1; p1 = A2 + (size_t)r1c*lda2; kk1 = k-K1; }
        float2 x00 = *(const float2*)(p0 + kk0 + 2*t);
        float2 x02 = *(const float2*)(p0 + kk0 + 2*t + 8);
        float2 x10 = *(const float2*)(p1 + kk1 + 2*t);
        float2 x12 = *(const float2*)(p1 + kk1 + 2*t + 8);
        u32 ah[4], al[4];
        split2(x00, ah[0], al[0]);
        split2(x10, ah[1], al[1]);
        split2(x02, ah[2], al[2]);
        split2(x12, ah[3], al[3]);
#pragma unroll
        for (int nt = 0; nt < NT; nt++){
            int n = nt*8 + gr;
            u32 bh[2], bl[2];
            bh[0] = *(const u32*)(BhA + n*K + k + 2*t);
            bh[1] = *(const u32*)(BhA + n*K + k + 8 + 2*t);
            bl[0] = *(const u32*)(BlA + n*K + k + 2*t);
            bl[1] = *(const u32*)(BlA + n*K + k + 8 + 2*t);
            mma16816(accA[nt], ah, bh);
            mma16816(accA[nt], ah, bl);
            mma16816(accA[nt], al, bh);
            bh[0] = *(const u32*)(BhB + n*K + k + 2*t);
            bh[1] = *(const u32*)(BhB + n*K + k + 8 + 2*t);
            bl[0] = *(const u32*)(BlB + n*K + k + 2*t);
            bl[1] = *(const u32*)(BlB + n*K + k + 8 + 2*t);
            mma16816(accB[nt], ah, bh);
            mma16816(accB[nt], ah, bl);
            mma16816(accB[nt], al, bh);
        }
    }
#pragma unroll
    for (int nt = 0; nt < NT; nt++){
        int c = nt*8 + 2*t;
        if (r0 < M){
            *(float2*)(OutA + (size_t)r0*64 + c) = make_float2(accA[nt][0], accA[nt][1]);
            *(float2*)(OutB + (size_t)r0*64 + c) = make_float2(accB[nt][0], accB[nt][1]);
        }
        if (r1 < M){
            *(float2*)(OutA + (size_t)r1*64 + c) = make_float2(accA[nt][2], accA[nt][3]);
            *(float2*)(OutB + (size_t)r1*64 + c) = make_float2(accB[nt][2], accB[nt][3]);
        }
    }
}

// ---- GAT alpha ----
__global__ void alpha_kernel(const float* __restrict__ att, int H){
    int i = blockIdx.x * blockDim.x + threadIdx.x;
    if (i >= NN*H) return;
    int n = i / H, h = i - n*H;
    int C = 64 / H;
    const float* xr = g_xh + (size_t)n*64 + h*C;
    const float* ar = att + h*C;
    float s = 0.f;
    for (int c = 0; c < C; c++) s = fmaf(xr[c], ar[c], s);
    g_alpha[i] = s;
}

// ---- GAT aggregate ----
__global__ void gatAgg_kernel(const float* __restrict__ bias,
                              float* __restrict__ outp, int H, int clean){
    int t = blockIdx.x * blockDim.x + threadIdx.x;
    int n = t >> 4;
    if (n >= NN) return;
    int l = t & 15;
    int h = (l*H) >> 4;
    int beg = g_off[n], end = g_off[n+1];

    float sum = 0.f;
    for (int p = beg; p < end; p++) sum += g_ea[p*H + h];
    float rinv = (end > beg) ? __fdividef(1.f, sum) : 0.f;

    float4 res = *(const float4*)(g_xh + (size_t)n*64 + l*4);
    float acc0 = res.x + bias[l*4], acc1 = res.y + bias[l*4+1];
    float acc2 = res.z + bias[l*4+2], acc3 = res.w + bias[l*4+3];

    int p = beg;
    for (; p + 4 <= end; p += 4){
        int s0 = g_srcCSR[p],   s1 = g_srcCSR[p+1];
        int s2 = g_srcCSR[p+2], s3 = g_srcCSR[p+3];
        float c0 = fmaf(g_ea[(p  )*H + h], rinv, g_escCSR[p  ]);
        float c1 = fmaf(g_ea[(p+1)*H + h], rinv, g_escCSR[p+1]);
        float c2 = fmaf(g_ea[(p+2)*H + h], rinv, g_escCSR[p+2]);
        float c3 = fmaf(g_ea[(p+3)*H + h], rinv, g_escCSR[p+3]);
        float4 v0 = *(const float4*)(g_xh + (size_t)s0*64 + l*4);
        float4 v1 = *(const float4*)(g_xh + (size_t)s1*64 + l*4);
        float4 v2 = *(const float4*)(g_xh + (size_t)s2*64 + l*4);
        float4 v3 = *(const float4*)(g_xh + (size_t)s3*64 + l*4);
        acc0 = fmaf(v0.x,c0, fmaf(v1.x,c1, fmaf(v2.x,c2, fmaf(v3.x,c3, acc0))));
        acc1 = fmaf(v0.y,c0, fmaf(v1.y,c1, fmaf(v2.y,c2, fmaf(v3.y,c3, acc1))));
        acc2 = fmaf(v0.z,c0, fmaf(v1.z,c1, fmaf(v2.z,c2, fmaf(v3.z,c3, acc2))));
        acc3 = fmaf(v0.w,c0, fmaf(v1.w,c1, fmaf(v2.w,c2, fmaf(v3.w,c3, acc3))));
    }
    for (; p < end; p++){
        int s = g_srcCSR[p];
        float cf = fmaf(g_ea[p*H + h], rinv, g_escCSR[p]);
        float4 xv = *(const float4*)(g_xh + (size_t)s*64 + l*4);
        acc0 = fmaf(xv.x, cf, acc0);
        acc1 = fmaf(xv.y, cf, acc1);
        acc2 = fmaf(xv.z, cf, acc2);
        acc3 = fmaf(xv.w, cf, acc3);
    }
    if (clean){
        if (!isfinite(acc0)) acc0 = 0.f;
        if (!isfinite(acc1)) acc1 = 0.f;
        if (!isfinite(acc2)) acc2 = 0.f;
        if (!isfinite(acc3)) acc3 = 0.f;
    }
    *(float4*)(outp + (size_t)n*64 + l*4) = make_float4(acc0, acc1, acc2, acc3);
}

// ---- GCN aggregate ----
__global__ void gcnAgg_kernel(const float* __restrict__ bias,
                              float* __restrict__ outp){
    int t = blockIdx.x * blockDim.x + threadIdx.x;
    int n = t >> 4;
    if (n >= NN) return;
    int l = t & 15;
    int beg = g_off[n], end = g_off[n+1];
    float di = g_dinv[n];

    float4 sv = *(const float4*)(g_xw + (size_t)n*64 + l*4);
    float dd = di * di;
    float acc0 = fmaf(sv.x, dd, bias[l*4]);
    float acc1 = fmaf(sv.y, dd, bias[l*4+1]);
    float acc2 = fmaf(sv.z, dd, bias[l*4+2]);
    float acc3 = fmaf(sv.w, dd, bias[l*4+3]);

    int p = beg;
    for (; p + 4 <= end; p += 4){
        int s0 = g_srcCSR[p],   s1 = g_srcCSR[p+1];
        int s2 = g_srcCSR[p+2], s3 = g_srcCSR[p+3];
        float c0 = g_nrmCSR[p]   * di;
        float c1 = g_nrmCSR[p+1] * di;
        float c2 = g_nrmCSR[p+2] * di;
        float c3 = g_nrmCSR[p+3] * di;
        float4 v0 = *(const float4*)(g_xw + (size_t)s0*64 + l*4);
        float4 v1 = *(const float4*)(g_xw + (size_t)s1*64 + l*4);
        float4 v2 = *(const float4*)(g_xw + (size_t)s2*64 + l*4);
        float4 v3 = *(const float4*)(g_xw + (size_t)s3*64 + l*4);
        acc0 = fmaf(v0.x,c0, fmaf(v1.x,c1, fmaf(v2.x,c2, fmaf(v3.x,c3, acc0))));
        acc1 = fmaf(v0.y,c0, fmaf(v1.y,c1, fmaf(v2.y,c2, fmaf(v3.y,c3, acc1))));
        acc2 = fmaf(v0.z,c0, fmaf(v1.z,c1, fmaf(v2.z,c2, fmaf(v3.z,c3, acc2))));
        acc3 = fmaf(v0.w,c0, fmaf(v1.w,c1, fmaf(v2.w,c2, fmaf(v3.w,c3, acc3))));
    }
    for (; p < end; p++){
        int s = g_srcCSR[p];
        float nm = g_nrmCSR[p] * di;
        float4 xv = *(const float4*)(g_xw + (size_t)s*64 + l*4);
        acc0 = fmaf(xv.x, nm, acc0);
        acc1 = fmaf(xv.y, nm, acc1);
        acc2 = fmaf(xv.z, nm, acc2);
        acc3 = fmaf(xv.w, nm, acc3);
    }
    acc0 = acc0 > 0.f ? acc0 : 0.01f*acc0;
    acc1 = acc1 > 0.f ? acc1 : 0.01f*acc1;
    acc2 = acc2 > 0.f ? acc2 : 0.01f*acc2;
    acc3 = acc3 > 0.f ? acc3 : 0.01f*acc3;
    *(float4*)(outp + (size_t)n*64 + l*4) = make_float4(acc0, acc1, acc2, acc3);
}

// ---- classifier layers 2+3 ----
__global__ void cls23_kernel(const float* __restrict__ W2, const float* __restrict__ b2,
                             const float* __restrict__ W3, const float* __restrict__ b3,
                             float* __restrict__ out){
    __shared__ float sW2[32*16], sW3[16*4], sb2[16], sb3[4];
    for (int i = threadIdx.x; i < 512; i += 256) sW2[i] = W2[i];
    for (int i = threadIdx.x; i < 64;  i += 256) sW3[i] = W3[i];
    if (threadIdx.x < 16) sb2[threadIdx.x] = b2[threadIdx.x];
    if (threadIdx.x < 4)  sb3[threadIdx.x] = b3[threadIdx.x];
    __syncthreads();
    int n = blockIdx.x * blockDim.x + threadIdx.x;
    if (n >= NN) return;
    float h2[16];
#pragma unroll
    for (int j = 0; j < 16; j++) h2[j] = sb2[j];
#pragma unroll
    for (int q = 0; q < 8; q++){
        float4 hv = *(const float4*)(g_h1 + (size_t)n*32 + q*4);
        float hh[4] = {hv.x, hv.y, hv.z, hv.w};
#pragma unroll
        for (int kk = 0; kk < 4; kk++)
#pragma unroll
            for (int j = 0; j < 16; j++) h2[j] = fmaf(hh[kk], sW2[(q*4+kk)*16 + j], h2[j]);
    }
#pragma unroll
    for (int j = 0; j < 16; j++) h2[j] = h2[j] > 0.f ? h2[j] : 0.01f*h2[j];
    float o[4] = {sb3[0], sb3[1], sb3[2], sb3[3]};
#pragma unroll
    for (int k = 0; k < 16; k++)
#pragma unroll
        for (int j = 0; j < 4; j++) o[j] = fmaf(h2[k], sW3[k*4 + j], o[j]);
    *(float4*)(out + (size_t)n*4) = make_float4(o[0], o[1], o[2], o[3]);
}

extern "C" void kernel_launch(void* const* d_in, const int* in_sizes, int n_in,
                              void* d_out, int out_size)
{
    const float* x    = (const float*)d_in[0];
    const float* eseq = (const float*)d_in[1];
    const float* nseq = (const float*)d_in[2];
    const float* Wih  = (const float*)d_in[3];
    const float* Whh  = (const float*)d_in[4];
    const float* lb   = (const float*)d_in[5];
    const float* dW   = (const float*)d_in[6];
    const float* dbv  = (const float*)d_in[7];
    const float* g1W  = (const float*)d_in[8];
    const float* g1att= (const float*)d_in[9];
    const float* g1b  = (const float*)d_in[10];
    const float* g2W  = (const float*)d_in[11];
    const float* g2att= (const float*)d_in[12];
    const float* g2b  = (const float*)d_in[13];
    const float* n1W  = (const float*)d_in[14];
    const float* n1b  = (const float*)d_in[15];
    const float* n2W  = (const float*)d_in[16];
    const float* n2b  = (const float*)d_in[17];
    const float* c1W  = (const float*)d_in[18];
    const float* c1b  = (const float*)d_in[19];
    const float* c2W  = (const float*)d_in[20];
    const float* c2b  = (const float*)d_in[21];
    const float* c3W  = (const float*)d_in[22];
    const float* c3b  = (const float*)d_in[23];
    const int*   ei   = (const int*)d_in[24];
    const int*   elen = (const int*)d_in[25];
    const int*   nlen = (const int*)d_in[26];

    float* out  = (float*)d_out;
    float* xgcn = out + (size_t)NN*4;
    float* xgat = xgcn + (size_t)NN*64;

    float *p_nf, *p_xh, *p_gat1, *p_xw, *p_gcn1, *p_h1;
    __nv_bfloat16 *bh1,*bl1,*bh2,*bl2,*bn1,*bn1l,*bn2,*bn2l,*bc1,*bc1l;
    cudaGetSymbolAddress((void**)&p_nf,   g_nf);
    cudaGetSymbolAddress((void**)&p_xh,   g_xh);
    cudaGetSymbolAddress((void**)&p_gat1, g_gat1);
    cudaGetSymbolAddress((void**)&p_xw,   g_xw);
    cudaGetSymbolAddress((void**)&p_gcn1, g_gcn1);
    cudaGetSymbolAddress((void**)&p_h1,   g_h1);
    cudaGetSymbolAddress((void**)&bh1,  g_bh1);  cudaGetSymbolAddress((void**)&bl1,  g_bl1);
    cudaGetSymbolAddress((void**)&bh2,  g_bh2);  cudaGetSymbolAddress((void**)&bl2,  g_bl2);
    cudaGetSymbolAddress((void**)&bn1,  g_bn1);  cudaGetSymbolAddress((void**)&bn1l, g_bn1l);
    cudaGetSymbolAddress((void**)&bn2,  g_bn2);  cudaGetSymbolAddress((void**)&bn2l, g_bn2l);
    cudaGetSymbolAddress((void**)&bc1,  g_bc1);  cudaGetSymbolAddress((void**)&bc1l, g_bc1l);

    static cudaStream_t s1 = nullptr, s2 = nullptr;
    static cudaEvent_t evRoot = nullptr, evXw = nullptr, evConv = nullptr,
                       evGcn = nullptr, evCsr = nullptr, evEscC = nullptr;
    if (!s1){
        cudaStreamCreateWithFlags(&s1, cudaStreamNonBlocking);
        cudaStreamCreateWithFlags(&s2, cudaStreamNonBlocking);
        cudaEventCreateWithFlags(&evRoot, cudaEventDisableTiming);
        cudaEventCreateWithFlags(&evXw,   cudaEventDisableTiming);
        cudaEventCreateWithFlags(&evConv, cudaEventDisableTiming);
        cudaEventCreateWithFlags(&evGcn,  cudaEventDisableTiming);
        cudaEventCreateWithFlags(&evCsr,  cudaEventDisableTiming);
        cudaEventCreateWithFlags(&evEscC, cudaEventDisableTiming);
    }

    auto cdiv = [](int a, int b){ return (a + b - 1) / b; };
    cudaStream_t s0 = 0;
    const int NBLK = cdiv(NN, 256);
    const int BIG = 1 << 30;

    cudaEventRecord(evRoot, s0);
    cudaStreamWaitEvent(s1, evRoot, 0);
    cudaStreamWaitEvent(s2, evRoot, 0);

    // ---- s1: edge LSTM -> esc; escCSR after CSR ready ----
    lstm_kernel<<<2048, 256, 0, s1>>>(eseq, elen, Wih, Whh, lb, dW, dbv, EE, 1);

    // ---- s2: CSR build (fillAdj also writes srcCSR + nrmCSR) ----
    zerocnt_kernel<<<NBLK, 256, 0, s2>>>();
    count_kernel<<<cdiv(EE,256), 256, 0, s2>>>(ei);
    scan1_kernel<<<NBLK, 256, 0, s2>>>();
    scan2_kernel<<<1, 256, 0, s2>>>(NBLK);
    scan3_kernel<<<NBLK, 256, 0, s2>>>();
    fillAdj_kernel<<<cdiv(EE,256), 256, 0, s2>>>(ei);
    cudaEventRecord(evCsr, s2);

    cudaStreamWaitEvent(s1, evCsr, 0);
    escCSR_kernel<<<cdiv(EE,256), 256, 0, s1>>>();
    cudaEventRecord(evEscC, s1);

    // ---- s0: weight conversion + node features + dual GEMM ----
    convw_all_kernel<<<cdiv(51200,256), 256, 0, s0>>>(g1W, g2W, n1W, n2W, c1W);
    cudaEventRecord(evConv, s0);
    lstm_kernel<<<512, 256, 0, s0>>>(nseq, nlen, Wih, Whh, lb, dW, dbv, NN, 0);
    gemm_dual_kernel<<<cdiv(NN,128), 256, 0, s0>>>(
        x, 240, 240, p_nf, 16, bh1, bl1, bn1, bn1l, p_xh, p_xw, NN, 256);
    cudaEventRecord(evXw, s0);

    // ---- s0: GAT chain ----
    alpha_kernel<<<cdiv(NN*8,256),256,0,s0>>>(g1att, 8);
    cudaStreamWaitEvent(s0, evCsr, 0);
    eaPrep_kernel<<<cdiv(EE,256),256,0,s0>>>(8);
    cudaStreamWaitEvent(s0, evEscC, 0);
    gatAgg_kernel<<<cdiv(NN*16,256),256,0,s0>>>(g1b, p_gat1, 8, 0);
    gemm_tc3_kernel<64><<<cdiv(NN,128),256,0,s0>>>(
        p_gat1, 64, BIG, nullptr, 0, BIG, nullptr, 0,
        bh2, bl2, nullptr, p_xh, NN, 64, 0);
    alpha_kernel<<<cdiv(NN,256),256,0,s0>>>(g2att, 1);
    eaPrep_kernel<<<cdiv(EE,256),256,0,s0>>>(1);
    gatAgg_kernel<<<cdiv(NN*16,256),256,0,s0>>>(g2b, xgat, 1, 1);

    // ---- s2: GCN chain (xw from dual gemm) ----
    cudaStreamWaitEvent(s2, evXw, 0);
    gcnAgg_kernel<<<cdiv(NN*16,256),256,0,s2>>>(n1b, p_gcn1);
    gemm_tc3_kernel<64><<<cdiv(NN,128),256,0,s2>>>(
        p_gcn1, 64, BIG, nullptr, 0, BIG, nullptr, 0,
        bn2, bn2l, nullptr, p_xw, NN, 64, 0);
    gcnAgg_kernel<<<cdiv(NN*16,256),256,0,s2>>>(n2b, xgcn);
    cudaEventRecord(evGcn, s2);

    // ---- join + classifier ----
    cudaStreamWaitEvent(s0, evGcn, 0);
    gemm_tc3_kernel<32><<<cdiv(NN,128),256,0,s0>>>(
        x, 240, 240, p_nf, 16, 256, xgcn, 64,
        bc1, bc1l, c1b, p_h1, NN, 320, 1);
    cls23_kernel<<<cdiv(NN,256),256,0,s0>>>(c2W, c2b, c3W, c3b, out);
}